// round 2
// baseline (speedup 1.0000x reference)
#include <cuda_runtime.h>

#define NV 20000
#define NC 84000
#define NG 200
#define NE 252000
#define RNDS 8
#define CEILDIV(a,b) (((a)+(b)-1)/(b))

// ---------------- scratch (device globals; allocated at module load) ----------------
__device__ float d_variables[NV*64];
__device__ float d_clause_state[NC*64];
__device__ float d_v1[NV*68];
__device__ float d_hq[NV*64];
__device__ float d_query[NV*64];
__device__ float d_closs[NC*64];
__device__ float d_cu[NC*128];
__device__ float d_hc[NC*128];
__device__ float d_cdata[NC*128];
__device__ float d_unit[NV*256];
__device__ float d_hu1[NV*128];
__device__ float d_hu2[NV*128];
__device__ float d_uout[NV*64];
__device__ float d_ho[NV*64];
__device__ float d_logits[NV];
__device__ float d_last_logits[NV];

__device__ float d_var_sum[2*NV];
__device__ float d_lit_deg[2*NV];
__device__ float d_degw[2*NV];
__device__ float d_vdw[NV];
__device__ float d_vmask[NV];
__device__ float d_vg_norm[NV];
__device__ float d_cg_norm[NC];
__device__ float d_vmask_gsum[NG];
__device__ float d_wsig_gsum[NG];
__device__ float d_loss_sum[NG];
__device__ float d_pg[NG];
__device__ float d_mean[NG*64];
__device__ float d_varred[NG];

__device__ int d_counts[2*NV];
__device__ int d_csroff[2*NV+1];
__device__ int d_cursor[2*NV];
__device__ int d_csredge[NE];
__device__ int d_cstart[NG+1];
__device__ int d_vstart[NG+1];
__device__ int d_done;
__device__ int d_allsat;
__device__ int d_step;

// ---------------- helpers ----------------
__device__ __forceinline__ float sp_f(float x){ return fmaxf(x,0.f)+log1pf(expf(-fabsf(x))); }
__device__ __forceinline__ float sigm(float x){ return 1.f/(1.f+expf(-x)); }

// ---------------- init ----------------
__global__ void k_init(){
    int i = blockIdx.x*blockDim.x + threadIdx.x;
    if (i < 2*NV){ d_var_sum[i]=0.f; d_lit_deg[i]=0.f; d_counts[i]=0; d_cursor[i]=0; }
    if (i < NG){ d_vmask_gsum[i]=0.f; d_wsig_gsum[i]=0.f; d_loss_sum[i]=0.f; }
    if (i <= NG){ d_cstart[i]=NC; d_vstart[i]=NV; }
    if (i == 0){ d_done=0; d_allsat=1; d_step=0; d_csroff[2*NV]=NE; }
}

__global__ void k_init_state(){
    int i = blockIdx.x*blockDim.x + threadIdx.x;
    if (i < NC*64) d_clause_state[i]=1.f;
    if (i < NV*64) d_variables[i]=1.f;
}

__global__ void k_edge_scatter(const int* __restrict__ elit, const int* __restrict__ eclause,
                               const float* __restrict__ wsig, const float* __restrict__ wsp){
    int e = blockIdx.x*blockDim.x + threadIdx.x;
    if (e >= NE) return;
    int c = eclause[e];
    int l = elit[e];
    float w = wsig[c];
    atomicAdd(&d_var_sum[l], w*wsp[c]);
    atomicAdd(&d_lit_deg[l], w);
    atomicAdd(&d_counts[l], 1);
}

__global__ void k_scan(){
    __shared__ int s[1024];
    int tid = threadIdx.x;
    int carry = 0;
    for (int base=0; base<2*NV; base+=1024){
        int i = base+tid;
        int v = (i<2*NV)? d_counts[i] : 0;
        s[tid] = v; __syncthreads();
        for (int off=1; off<1024; off<<=1){
            int t = (tid>=off)? s[tid-off] : 0;
            __syncthreads();
            s[tid] += t;
            __syncthreads();
        }
        if (i<2*NV) d_csroff[i] = carry + s[tid] - v;
        carry += s[1023];
        __syncthreads();
    }
}

__global__ void k_fill(const int* __restrict__ elit){
    int e = blockIdx.x*blockDim.x + threadIdx.x;
    if (e >= NE) return;
    int l = elit[e];
    int p = atomicAdd(&d_cursor[l], 1);
    d_csredge[d_csroff[l]+p] = e;
}

__global__ void k_segmin(const int* __restrict__ cgid, const int* __restrict__ vgid){
    int i = blockIdx.x*blockDim.x + threadIdx.x;
    if (i < NC) atomicMin(&d_cstart[cgid[i]], i);
    if (i < NV) atomicMin(&d_vstart[vgid[i]], i);
}

__global__ void k_segfix(){
    if (threadIdx.x==0){
        d_cstart[NG]=NC;
        for (int g=NG-1; g>=0; g--) d_cstart[g]=min(d_cstart[g], d_cstart[g+1]);
    }
    if (threadIdx.x==1){
        d_vstart[NG]=NV;
        for (int g=NG-1; g>=0; g--) d_vstart[g]=min(d_vstart[g], d_vstart[g+1]);
    }
}

__global__ void k_var_pre(const int* __restrict__ vgid){
    int v = blockIdx.x*blockDim.x + threadIdx.x;
    if (v >= NV) return;
    float m = 1.f - expf(-(d_var_sum[v] + d_var_sum[v+NV]));
    d_vmask[v] = m;
    atomicAdd(&d_vmask_gsum[vgid[v]], m);
    float dp = d_lit_deg[v], dn = d_lit_deg[v+NV];
    d_degw[v]    = rsqrtf(fmaxf(dp,1.f));
    d_degw[v+NV] = rsqrtf(fmaxf(dn,1.f));
    d_vdw[v]     = 4.f*rsqrtf(fmaxf(dp+dn,1.f));
}

__global__ void k_clause_pre(const int* __restrict__ cgid, const float* __restrict__ wsig){
    int c = blockIdx.x*blockDim.x + threadIdx.x;
    if (c >= NC) return;
    atomicAdd(&d_wsig_gsum[cgid[c]], wsig[c]);
}

__global__ void k_norms(const int* __restrict__ cgid, const int* __restrict__ vgid,
                        const float* __restrict__ wsig){
    int i = blockIdx.x*blockDim.x + threadIdx.x;
    if (i < NC){
        float s = d_wsig_gsum[cgid[i]];
        d_cg_norm[i] = wsig[i] * (s>0.f ? 1.f/s : 0.f);
    }
    if (i < NV){
        float s = d_vmask_gsum[vgid[i]];
        d_vg_norm[i] = d_vmask[i] * (s>0.f ? 1.f/s : 0.f);
    }
}

// ---------------- generic fused row-linear: Y[M,N] = act(X[M,K] @ W[K,N] + B) ----------------
__global__ void k_linear(const float* __restrict__ X, const float* __restrict__ W,
                         const float* __restrict__ B, float* __restrict__ Y,
                         int M, int K, int N, int doRelu){
    extern __shared__ float smx[];
    int wid = threadIdx.x>>5, lane = threadIdx.x&31;
    int row = blockIdx.x*(blockDim.x>>5) + wid;
    float* x = smx + wid*K;
    if (row < M){
        const float* xr = X + (size_t)row*K;
        #pragma unroll 4
        for (int k=lane; k<K; k+=32) x[k]=xr[k];
    }
    __syncwarp();
    if (row >= M) return;
    if (N == 128){
        float4 acc = __ldg((const float4*)B + lane);
        const float4* Wp = (const float4*)W + lane;
        #pragma unroll 4
        for (int k=0;k<K;k++){
            float xk = x[k];
            float4 wv = __ldg(Wp + (size_t)k*32);
            acc.x = fmaf(xk,wv.x,acc.x);
            acc.y = fmaf(xk,wv.y,acc.y);
            acc.z = fmaf(xk,wv.z,acc.z);
            acc.w = fmaf(xk,wv.w,acc.w);
        }
        if (doRelu){ acc.x=fmaxf(acc.x,0.f); acc.y=fmaxf(acc.y,0.f); acc.z=fmaxf(acc.z,0.f); acc.w=fmaxf(acc.w,0.f); }
        ((float4*)(Y+(size_t)row*128))[lane] = acc;
    } else { // N == 64
        float2 acc = __ldg((const float2*)B + lane);
        const float2* Wp = (const float2*)W + lane;
        #pragma unroll 4
        for (int k=0;k<K;k++){
            float xk = x[k];
            float2 wv = __ldg(Wp + (size_t)k*32);
            acc.x = fmaf(xk,wv.x,acc.x);
            acc.y = fmaf(xk,wv.y,acc.y);
        }
        if (doRelu){ acc.x=fmaxf(acc.x,0.f); acc.y=fmaxf(acc.y,0.f); }
        ((float2*)(Y+(size_t)row*64))[lane] = acc;
    }
}

// ---------------- per-round kernels ----------------
__global__ void k_build_v1(const float* __restrict__ noise_t){
    int i = blockIdx.x*blockDim.x + threadIdx.x;
    if (i >= NV*68) return;
    int v = i/68, col = i-v*68;
    d_v1[i] = (col<64) ? d_variables[v*64+col] : noise_t[v*4 + (col-64)];
}

// per-clause: cval from query (softplus literals), clauses_loss = exp(-cval)
__global__ void k_clause_cval(const int* __restrict__ elit, const float* __restrict__ wsig){
    int gw = (blockIdx.x*blockDim.x + threadIdx.x)>>5;
    int lane = threadIdx.x & 31;
    if (gw >= NC) return;
    int c = gw;
    float w = wsig[c];
    float2 acc = {0.f,0.f};
    #pragma unroll
    for (int j=0;j<3;j++){
        int l = elit[3*c+j];
        int v = (l<NV)? l : l-NV;
        float sgn = (l<NV)? 1.f : -1.f;
        float2 q = *(const float2*)(d_query + (size_t)v*64 + lane*2);
        acc.x += sp_f(sgn*q.x);
        acc.y += sp_f(sgn*q.y);
    }
    float2 cl = { expf(-w*acc.x), expf(-w*acc.y) };
    *(float2*)(d_closs + (size_t)c*64 + lane*2) = cl;
}

// per-variable: analytic VJP grad -> unit[:,0:64], copy variables -> unit[:,64:128]
__global__ void k_var_grad(const float* __restrict__ wsig){
    int gw = (blockIdx.x*blockDim.x + threadIdx.x)>>5;
    int lane = threadIdx.x & 31;
    if (gw >= NV) return;
    int v = gw;
    float2 ap={0.f,0.f}, an={0.f,0.f};
    int s0=d_csroff[v], e0=d_csroff[v+1];
    for (int i=s0;i<e0;i++){
        int e=d_csredge[i]; int c=e/3;
        float w=wsig[c];
        float2 cl=*(const float2*)(d_closs+(size_t)c*64+lane*2);
        ap.x += w*cl.x; ap.y += w*cl.y;
    }
    int s1=d_csroff[NV+v], e1=d_csroff[NV+v+1];
    for (int i=s1;i<e1;i++){
        int e=d_csredge[i]; int c=e/3;
        float w=wsig[c];
        float2 cl=*(const float2*)(d_closs+(size_t)c*64+lane*2);
        an.x += w*cl.x; an.y += w*cl.y;
    }
    float2 q = *(const float2*)(d_query + (size_t)v*64 + lane*2);
    float vd = d_vdw[v];
    float2 g;
    g.x = (-ap.x*sigm(q.x) + an.x*sigm(-q.x)) * vd;
    g.y = (-ap.y*sigm(q.y) + an.y*sigm(-q.y)) * vd;
    *(float2*)(d_unit + (size_t)v*256 + lane*2) = g;
    float2 vv = *(const float2*)(d_variables + (size_t)v*64 + lane*2);
    *(float2*)(d_unit + (size_t)v*256 + 64 + lane*2) = vv;
}

__global__ void k_build_cu(){
    int i = blockIdx.x*blockDim.x + threadIdx.x;
    if (i >= NC*128) return;
    int c = i>>7, col = i&127;
    d_cu[i] = (col<64) ? d_clause_state[(size_t)c*64+col] : 4.f*d_closs[(size_t)c*64+(col-64)];
}

// ---------------- pair_norm (mode 0: clause, mode 1: variable) ----------------
__global__ void k_pn_mean(int mode){
    const float* x; const float* w; const int* st; int stride;
    if (mode==0){ x=d_cdata+64; w=d_cg_norm; st=d_cstart; stride=128; }
    else        { x=d_uout;    w=d_vg_norm; st=d_vstart; stride=64;  }
    int g=blockIdx.x;
    int s=st[g], e=st[g+1];
    int f=threadIdx.x&63, grp=threadIdx.x>>6;
    float acc=0.f;
    for (int r=s+grp; r<e; r+=4) acc += w[r]*x[(size_t)r*stride+f];
    __shared__ float red[256];
    red[threadIdx.x]=acc; __syncthreads();
    if (grp==0) d_mean[g*64+f] = red[f]+red[64+f]+red[128+f]+red[192+f];
}

__global__ void k_pn_var(int mode){
    const float* x; const float* w; const int* st; int stride;
    if (mode==0){ x=d_cdata+64; w=d_cg_norm; st=d_cstart; stride=128; }
    else        { x=d_uout;    w=d_vg_norm; st=d_vstart; stride=64;  }
    int g=blockIdx.x;
    int s=st[g], e=st[g+1];
    int f=threadIdx.x&63, grp=threadIdx.x>>6;
    float m = d_mean[g*64+f];
    float acc=0.f;
    for (int r=s+grp; r<e; r+=4){
        float xc = x[(size_t)r*stride+f]-m;
        acc += w[r]*xc*xc;
    }
    __shared__ float red[256];
    red[threadIdx.x]=acc; __syncthreads();
    for (int o=128;o;o>>=1){ if (threadIdx.x<o) red[threadIdx.x]+=red[threadIdx.x+o]; __syncthreads(); }
    if (threadIdx.x==0) d_varred[g]=red[0]*(1.f/64.f);
}

__global__ void k_pn_apply(int mode, const int* __restrict__ gid, int M){
    if (d_done) return;
    int i = blockIdx.x*blockDim.x + threadIdx.x;
    if (i >= M*64) return;
    int r = i>>6, f = i&63;
    const float* x; float* state; int stride;
    if (mode==0){ x=d_cdata+64; state=d_clause_state; stride=128; }
    else        { x=d_uout;    state=d_variables;    stride=64;  }
    int g = gid[r];
    float xc = x[(size_t)r*stride+f] - d_mean[g*64+f];
    float nrm = xc * rsqrtf(d_varred[g]+1e-6f) * 0.25f;
    state[i] = nrm + 0.1f*state[i];
}

// per-variable: variables_loss (pos/neg) -> unit[:,128:256]
__global__ void k_var_loss(const float* __restrict__ wsig){
    int gw = (blockIdx.x*blockDim.x + threadIdx.x)>>5;
    int lane = threadIdx.x & 31;
    if (gw >= NV) return;
    int v = gw;
    float2 ap={0.f,0.f}, an={0.f,0.f};
    int s0=d_csroff[v], e0=d_csroff[v+1];
    for (int i=s0;i<e0;i++){
        int e=d_csredge[i]; int c=e/3;
        float w=wsig[c];
        float2 cl=*(const float2*)(d_cdata+(size_t)c*128+lane*2);
        ap.x += w*cl.x; ap.y += w*cl.y;
    }
    int s1=d_csroff[NV+v], e1=d_csroff[NV+v+1];
    for (int i=s1;i<e1;i++){
        int e=d_csredge[i]; int c=e/3;
        float w=wsig[c];
        float2 cl=*(const float2*)(d_cdata+(size_t)c*128+lane*2);
        an.x += w*cl.x; an.y += w*cl.y;
    }
    float dp = d_degw[v], dn = d_degw[NV+v];
    float2 op = {ap.x*dp, ap.y*dp};
    float2 on = {an.x*dn, an.y*dn};
    *(float2*)(d_unit + (size_t)v*256 + 128 + lane*2) = op;
    *(float2*)(d_unit + (size_t)v*256 + 192 + lane*2) = on;
}

__global__ void k_logits(const float* __restrict__ ow2, const float* __restrict__ ob2){
    if (blockIdx.x==0 && threadIdx.x==0) d_allsat = 1;
    int gw = (blockIdx.x*blockDim.x + threadIdx.x)>>5;
    int lane = threadIdx.x & 31;
    if (gw >= NV) return;
    float a=0.f;
    for (int f=lane; f<64; f+=32) a += d_ho[(size_t)gw*64+f]*ow2[f];
    for (int o=16;o;o>>=1) a += __shfl_down_sync(0xffffffffu, a, o);
    if (lane==0){
        float lg = a + ob2[0];
        d_logits[gw] = lg;
        if (!d_done) d_last_logits[gw] = lg;
    }
}

// per-graph: final clause loss + satisfiability check
__global__ void k_final_clause(const int* __restrict__ elit, const float* __restrict__ wsig){
    int g = blockIdx.x;
    int s = d_cstart[g], e = d_cstart[g+1];
    float lsum=0.f; int sat=1;
    for (int c=s+threadIdx.x; c<e; c+=blockDim.x){
        float w = wsig[c];
        float cvs=0.f, csat=0.f;
        #pragma unroll
        for (int j=0;j<3;j++){
            int l = elit[3*c+j];
            int v = (l<NV)? l : l-NV;
            float sgn = (l<NV)? 1.f : -1.f;
            float lg = d_logits[v];
            cvs += sp_f(sgn*lg);
            float a = (lg>0.f)? 1.f : 0.f;          // round(sigmoid(lg)) with half-even at lg==0
            float lit01 = (l<NV)? a : 1.f-a;
            csat += w*lit01;
        }
        float cv = expf(-w*cvs);
        float pc = cv * (-logf(1.f - cv + 1e-10f));
        lsum += pc*w;
        if (csat < 1.f) sat = 0;
    }
    __shared__ float sred[256];
    __shared__ int ssat[256];
    sred[threadIdx.x]=lsum; ssat[threadIdx.x]=sat; __syncthreads();
    for (int o=128;o;o>>=1){
        if (threadIdx.x<o){ sred[threadIdx.x]+=sred[threadIdx.x+o]; ssat[threadIdx.x]&=ssat[threadIdx.x+o]; }
        __syncthreads();
    }
    if (threadIdx.x==0){
        d_pg[g]=sred[0];
        if (!ssat[0]) d_allsat = 0;
    }
}

__global__ void k_finish(){
    int done0 = d_done;
    if (!done0){
        for (int g=threadIdx.x; g<NG; g+=blockDim.x)
            d_loss_sum[g] += sqrtf(d_pg[g]+1e-6f) - 0.001f;
    }
    __syncthreads();
    if (threadIdx.x==0 && !done0){
        d_step++;
        if (d_allsat) d_done = 1;
    }
}

__global__ void k_output(float* __restrict__ out, int n){
    int i = blockIdx.x*blockDim.x + threadIdx.x;
    if (i >= n) return;
    float v;
    if (i < NV)            v = d_last_logits[i];
    else if (i < NV+NG)    v = d_loss_sum[i-NV]*(1.f/(float)RNDS);
    else if (i == NV+NG)   v = (float)d_step;
    else                   v = 0.f;
    out[i] = v;
}

// ---------------- host ----------------
static void run_linear(const float* X, const float* W, const float* B, float* Y,
                       int M, int K, int N, int relu){
    int warps = 8;
    dim3 blk(256), grd(CEILDIV(M, warps));
    k_linear<<<grd, blk, warps*K*(int)sizeof(float)>>>(X, W, B, Y, M, K, N, relu);
}

extern "C" void kernel_launch(void* const* d_in, const int* in_sizes, int n_in,
                              void* d_out, int out_size){
    const float* wsig   = (const float*)d_in[0];
    const float* wsp    = (const float*)d_in[1];
    const float* noise  = (const float*)d_in[2];
    const int*   elit   = (const int*)d_in[3];
    const int*   eclause= (const int*)d_in[4];
    const int*   cgid   = (const int*)d_in[5];
    const int*   vgid   = (const int*)d_in[6];
    const float* P[18];
    for (int i=0;i<18;i++) P[i]=(const float*)d_in[7+i];
    const float *qw1=P[0],*qb1=P[1],*qw2=P[2],*qb2=P[3];
    const float *cw1=P[4],*cb1=P[5],*cw2=P[6],*cb2=P[7];
    const float *uw1=P[8],*ub1=P[9],*uw2=P[10],*ub2=P[11],*uw3=P[12],*ub3=P[13];
    const float *ow1=P[14],*ob1=P[15],*ow2=P[16],*ob2=P[17];

    float *p_v1,*p_hq,*p_query,*p_cu,*p_hc,*p_cdata,*p_unit,*p_hu1,*p_hu2,*p_uout,*p_vars,*p_ho;
    cudaGetSymbolAddress((void**)&p_v1,    d_v1);
    cudaGetSymbolAddress((void**)&p_hq,    d_hq);
    cudaGetSymbolAddress((void**)&p_query, d_query);
    cudaGetSymbolAddress((void**)&p_cu,    d_cu);
    cudaGetSymbolAddress((void**)&p_hc,    d_hc);
    cudaGetSymbolAddress((void**)&p_cdata, d_cdata);
    cudaGetSymbolAddress((void**)&p_unit,  d_unit);
    cudaGetSymbolAddress((void**)&p_hu1,   d_hu1);
    cudaGetSymbolAddress((void**)&p_hu2,   d_hu2);
    cudaGetSymbolAddress((void**)&p_uout,  d_uout);
    cudaGetSymbolAddress((void**)&p_vars,  d_variables);
    cudaGetSymbolAddress((void**)&p_ho,    d_ho);

    // ---- init / precompute ----
    k_init<<<CEILDIV(2*NV,256),256>>>();
    k_init_state<<<CEILDIV(NC*64,256),256>>>();
    k_edge_scatter<<<CEILDIV(NE,256),256>>>(elit, eclause, wsig, wsp);
    k_scan<<<1,1024>>>();
    k_fill<<<CEILDIV(NE,256),256>>>(elit);
    k_segmin<<<CEILDIV(NC,256),256>>>(cgid, vgid);
    k_segfix<<<1,32>>>();
    k_var_pre<<<CEILDIV(NV,256),256>>>(vgid);
    k_clause_pre<<<CEILDIV(NC,256),256>>>(cgid, wsig);
    k_norms<<<CEILDIV(NC,256),256>>>(cgid, vgid, wsig);

    // ---- rounds ----
    for (int t=0; t<RNDS; t++){
        const float* nt = noise + (size_t)t*NV*4;
        k_build_v1<<<CEILDIV(NV*68,256),256>>>(nt);
        run_linear(p_v1, qw1, qb1, p_hq,    NV, 68, 64, 1);
        run_linear(p_hq, qw2, qb2, p_query, NV, 64, 64, 0);
        k_clause_cval<<<CEILDIV(NC*32,256),256>>>(elit, wsig);
        k_var_grad<<<CEILDIV(NV*32,256),256>>>(wsig);
        k_build_cu<<<CEILDIV(NC*128,256),256>>>();
        run_linear(p_cu, cw1, cb1, p_hc,    NC, 128, 128, 1);
        run_linear(p_hc, cw2, cb2, p_cdata, NC, 128, 128, 0);
        k_pn_mean<<<NG,256>>>(0);
        k_pn_var<<<NG,256>>>(0);
        k_pn_apply<<<CEILDIV(NC*64,256),256>>>(0, cgid, NC);
        k_var_loss<<<CEILDIV(NV*32,256),256>>>(wsig);
        run_linear(p_unit, uw1, ub1, p_hu1, NV, 256, 128, 1);
        run_linear(p_hu1,  uw2, ub2, p_hu2, NV, 128, 128, 1);
        run_linear(p_hu2,  uw3, ub3, p_uout,NV, 128, 64, 0);
        k_pn_mean<<<NG,256>>>(1);
        k_pn_var<<<NG,256>>>(1);
        k_pn_apply<<<CEILDIV(NV*64,256),256>>>(1, vgid, NV);
        run_linear(p_vars, ow1, ob1, p_ho, NV, 64, 64, 1);
        k_logits<<<CEILDIV(NV*32,256),256>>>(ow2, ob2);
        k_final_clause<<<NG,256>>>(elit, wsig);
        k_finish<<<1,256>>>();
    }

    k_output<<<CEILDIV(out_size>0?out_size:1,256),256>>>((float*)d_out, out_size);
}

// round 3
// speedup vs baseline: 1.9128x; 1.9128x over previous
#include <cuda_runtime.h>

#define NV 20000
#define NC 84000
#define NG 200
#define NE 252000
#define RNDS 8
#define CEILDIV(a,b) (((a)+(b)-1)/(b))

// ---------------- scratch (device globals; allocated at module load) ----------------
__device__ __align__(16) float d_variables[NV*64];
__device__ __align__(16) float d_clause_state[NC*64];
__device__ __align__(16) float d_hq[NV*64];
__device__ __align__(16) float d_query[NV*64];
__device__ __align__(16) float d_closs[NC*64];
__device__ __align__(16) float d_hc[NC*128];
__device__ __align__(16) float d_cdata[NC*128];
__device__ __align__(16) float d_unit[NV*256];
__device__ __align__(16) float d_hu1[NV*128];
__device__ __align__(16) float d_hu2[NV*128];
__device__ __align__(16) float d_uout[NV*64];
__device__ __align__(16) float d_ho[NV*64];
__device__ float d_logits[NV];
__device__ float d_last_logits[NV];

__device__ float d_var_sum[2*NV];
__device__ float d_lit_deg[2*NV];
__device__ float d_degw[2*NV];
__device__ float d_vdw[NV];
__device__ float d_vmask[NV];
__device__ float d_vg_norm[NV];
__device__ float d_cg_norm[NC];
__device__ float d_vmask_gsum[NG];
__device__ float d_wsig_gsum[NG];
__device__ float d_loss_sum[NG];
__device__ float d_pg[NG];
__device__ float d_mean[NG*64];
__device__ float d_varred[NG];

__device__ int d_counts[2*NV];
__device__ int d_csroff[2*NV+1];
__device__ int d_cursor[2*NV];
__device__ int d_csredge[NE];
__device__ int d_cstart[NG+1];
__device__ int d_vstart[NG+1];
__device__ int d_done;
__device__ int d_allsat;
__device__ int d_step;

// ---------------- helpers ----------------
__device__ __forceinline__ float sp_f(float x){ return fmaxf(x,0.f)+log1pf(expf(-fabsf(x))); }
__device__ __forceinline__ float sigm(float x){ return 1.f/(1.f+expf(-x)); }

// ---------------- init ----------------
__global__ void k_init(){
    int i = blockIdx.x*blockDim.x + threadIdx.x;
    if (i < 2*NV){ d_var_sum[i]=0.f; d_lit_deg[i]=0.f; d_counts[i]=0; d_cursor[i]=0; }
    if (i < NG){ d_vmask_gsum[i]=0.f; d_wsig_gsum[i]=0.f; d_loss_sum[i]=0.f; }
    if (i <= NG){ d_cstart[i]=NC; d_vstart[i]=NV; }
    if (i == 0){ d_done=0; d_allsat=1; d_step=0; d_csroff[2*NV]=NE; }
}

__global__ void k_init_state(){
    int i = blockIdx.x*blockDim.x + threadIdx.x;
    if (i < NC*64) d_clause_state[i]=1.f;
    if (i < NV*64) d_variables[i]=1.f;
}

__global__ void k_edge_scatter(const int* __restrict__ elit, const int* __restrict__ eclause,
                               const float* __restrict__ wsig, const float* __restrict__ wsp){
    int e = blockIdx.x*blockDim.x + threadIdx.x;
    if (e >= NE) return;
    int c = eclause[e];
    int l = elit[e];
    float w = wsig[c];
    atomicAdd(&d_var_sum[l], w*wsp[c]);
    atomicAdd(&d_lit_deg[l], w);
    atomicAdd(&d_counts[l], 1);
}

// chunked parallel scan: each thread owns 40 consecutive literals
__global__ void k_scan(){
    __shared__ int sh[1024];
    int tid = threadIdx.x;
    const int PER = 40;                // 1024*40 >= 2*NV
    int base = tid*PER;
    int sum = 0;
    for (int i=base; i<base+PER && i<2*NV; i++) sum += d_counts[i];
    sh[tid]=sum; __syncthreads();
    for (int off=1; off<1024; off<<=1){
        int t = (tid>=off)? sh[tid-off] : 0;
        __syncthreads();
        sh[tid]+=t;
        __syncthreads();
    }
    int run = sh[tid]-sum;             // exclusive prefix
    for (int i=base; i<base+PER && i<2*NV; i++){ d_csroff[i]=run; run+=d_counts[i]; }
}

__global__ void k_fill(const int* __restrict__ elit){
    int e = blockIdx.x*blockDim.x + threadIdx.x;
    if (e >= NE) return;
    int l = elit[e];
    int p = atomicAdd(&d_cursor[l], 1);
    d_csredge[d_csroff[l]+p] = e;
}

__global__ void k_segmin(const int* __restrict__ cgid, const int* __restrict__ vgid){
    int i = blockIdx.x*blockDim.x + threadIdx.x;
    if (i < NC) atomicMin(&d_cstart[cgid[i]], i);
    if (i < NV) atomicMin(&d_vstart[vgid[i]], i);
}

__global__ void k_segfix(){
    if (threadIdx.x==0){
        d_cstart[NG]=NC;
        for (int g=NG-1; g>=0; g--) d_cstart[g]=min(d_cstart[g], d_cstart[g+1]);
    }
    if (threadIdx.x==1){
        d_vstart[NG]=NV;
        for (int g=NG-1; g>=0; g--) d_vstart[g]=min(d_vstart[g], d_vstart[g+1]);
    }
}

__global__ void k_var_pre(const int* __restrict__ vgid){
    int v = blockIdx.x*blockDim.x + threadIdx.x;
    if (v >= NV) return;
    float m = 1.f - expf(-(d_var_sum[v] + d_var_sum[v+NV]));
    d_vmask[v] = m;
    atomicAdd(&d_vmask_gsum[vgid[v]], m);
    float dp = d_lit_deg[v], dn = d_lit_deg[v+NV];
    d_degw[v]    = rsqrtf(fmaxf(dp,1.f));
    d_degw[v+NV] = rsqrtf(fmaxf(dn,1.f));
    d_vdw[v]     = 4.f*rsqrtf(fmaxf(dp+dn,1.f));
}

__global__ void k_clause_pre(const int* __restrict__ cgid, const float* __restrict__ wsig){
    int c = blockIdx.x*blockDim.x + threadIdx.x;
    if (c >= NC) return;
    atomicAdd(&d_wsig_gsum[cgid[c]], wsig[c]);
}

__global__ void k_norms(const int* __restrict__ cgid, const int* __restrict__ vgid,
                        const float* __restrict__ wsig){
    int i = blockIdx.x*blockDim.x + threadIdx.x;
    if (i < NC){
        float s = d_wsig_gsum[cgid[i]];
        d_cg_norm[i] = wsig[i] * (s>0.f ? 1.f/s : 0.f);
    }
    if (i < NV){
        float s = d_vmask_gsum[vgid[i]];
        d_vg_norm[i] = d_vmask[i] * (s>0.f ? 1.f/s : 0.f);
    }
}

// ============== tiled GEMM: Y[M,N] = act(concat(X1, scale2*X2, 0) @ W[Ktrue,N] + B) ==============
// BM=128, BK=16. X logical row = [X1 (K1 cols) | scale2*X2 (K2 cols) | zeros up to Kp]
// K1, K2 multiples of 4; Kp multiple of 16.

#define BM 128
#define BK 16

__global__ void __launch_bounds__(256, 2)
k_gemm_n128(const float* __restrict__ X1, const float* __restrict__ X2, float scale2,
            int K1, int K2,
            const float* __restrict__ W, const float* __restrict__ Bias,
            float* __restrict__ Y, int M, int Kp, int Ktrue, int relu)
{
    __shared__ float Xs[BK*BM];
    __shared__ float Ws[BK*128];
    int tid = threadIdx.x;
    int m0 = blockIdx.x*BM;
    int rg = tid>>4, cg = tid&15;

    float acc[8][8];
    #pragma unroll
    for (int i=0;i<8;i++)
        #pragma unroll
        for (int j=0;j<8;j++) acc[i][j]=0.f;

    for (int k0=0; k0<Kp; k0+=BK){
        // stage X tile (transposed into Xs[k][m])
        {
            int q = tid&3;
            int c = k0 + q*4;
            #pragma unroll
            for (int h=0; h<2; h++){
                int m = (tid>>2) + h*64;
                float4 v = {0.f,0.f,0.f,0.f};
                int gm = m0+m;
                if (gm < M){
                    if (c < K1) v = *(const float4*)(X1 + (size_t)gm*K1 + c);
                    else if (K2 && c < K1+K2){
                        v = *(const float4*)(X2 + (size_t)gm*K2 + (c-K1));
                        v.x*=scale2; v.y*=scale2; v.z*=scale2; v.w*=scale2;
                    }
                }
                Xs[(q*4+0)*BM+m]=v.x; Xs[(q*4+1)*BM+m]=v.y;
                Xs[(q*4+2)*BM+m]=v.z; Xs[(q*4+3)*BM+m]=v.w;
            }
        }
        // stage W tile
        {
            int quad = tid&31;
            #pragma unroll
            for (int h=0; h<2; h++){
                int kr = (tid>>5) + h*8;
                float4 v = {0.f,0.f,0.f,0.f};
                if (k0+kr < Ktrue) v = *(const float4*)(W + (size_t)(k0+kr)*128 + quad*4);
                *(float4*)(Ws + kr*128 + quad*4) = v;
            }
        }
        __syncthreads();
        #pragma unroll
        for (int k=0;k<BK;k++){
            float4 a0 = *(const float4*)(Xs + k*BM + rg*4);
            float4 a1 = *(const float4*)(Xs + k*BM + 64 + rg*4);
            float4 b0 = *(const float4*)(Ws + k*128 + cg*4);
            float4 b1 = *(const float4*)(Ws + k*128 + 64 + cg*4);
            float a[8]={a0.x,a0.y,a0.z,a0.w,a1.x,a1.y,a1.z,a1.w};
            float b[8]={b0.x,b0.y,b0.z,b0.w,b1.x,b1.y,b1.z,b1.w};
            #pragma unroll
            for (int i=0;i<8;i++)
                #pragma unroll
                for (int j=0;j<8;j++) acc[i][j] = fmaf(a[i], b[j], acc[i][j]);
        }
        __syncthreads();
    }
    float4 bb0 = *(const float4*)(Bias + cg*4);
    float4 bb1 = *(const float4*)(Bias + 64 + cg*4);
    float bb[8]={bb0.x,bb0.y,bb0.z,bb0.w,bb1.x,bb1.y,bb1.z,bb1.w};
    #pragma unroll
    for (int i=0;i<8;i++){
        int m = m0 + ((i<4)? rg*4+i : 64+rg*4+(i-4));
        if (m >= M) continue;
        float o[8];
        #pragma unroll
        for (int j=0;j<8;j++){
            float t = acc[i][j]+bb[j];
            o[j] = relu? fmaxf(t,0.f) : t;
        }
        *(float4*)(Y + (size_t)m*128 + cg*4)      = make_float4(o[0],o[1],o[2],o[3]);
        *(float4*)(Y + (size_t)m*128 + 64 + cg*4) = make_float4(o[4],o[5],o[6],o[7]);
    }
}

__global__ void __launch_bounds__(256, 2)
k_gemm_n64(const float* __restrict__ X1, const float* __restrict__ X2, float scale2,
           int K1, int K2,
           const float* __restrict__ W, const float* __restrict__ Bias,
           float* __restrict__ Y, int M, int Kp, int Ktrue, int relu)
{
    __shared__ float Xs[BK*BM];
    __shared__ float Ws[BK*64];
    int tid = threadIdx.x;
    int m0 = blockIdx.x*BM;
    int rg = tid>>4, cg = tid&15;

    float acc[8][4];
    #pragma unroll
    for (int i=0;i<8;i++)
        #pragma unroll
        for (int j=0;j<4;j++) acc[i][j]=0.f;

    for (int k0=0; k0<Kp; k0+=BK){
        {
            int q = tid&3;
            int c = k0 + q*4;
            #pragma unroll
            for (int h=0; h<2; h++){
                int m = (tid>>2) + h*64;
                float4 v = {0.f,0.f,0.f,0.f};
                int gm = m0+m;
                if (gm < M){
                    if (c < K1) v = *(const float4*)(X1 + (size_t)gm*K1 + c);
                    else if (K2 && c < K1+K2){
                        v = *(const float4*)(X2 + (size_t)gm*K2 + (c-K1));
                        v.x*=scale2; v.y*=scale2; v.z*=scale2; v.w*=scale2;
                    }
                }
                Xs[(q*4+0)*BM+m]=v.x; Xs[(q*4+1)*BM+m]=v.y;
                Xs[(q*4+2)*BM+m]=v.z; Xs[(q*4+3)*BM+m]=v.w;
            }
        }
        {
            int kr = tid>>4, quad = tid&15;
            float4 v = {0.f,0.f,0.f,0.f};
            if (k0+kr < Ktrue) v = *(const float4*)(W + (size_t)(k0+kr)*64 + quad*4);
            *(float4*)(Ws + kr*64 + quad*4) = v;
        }
        __syncthreads();
        #pragma unroll
        for (int k=0;k<BK;k++){
            float4 a0 = *(const float4*)(Xs + k*BM + rg*4);
            float4 a1 = *(const float4*)(Xs + k*BM + 64 + rg*4);
            float4 b0 = *(const float4*)(Ws + k*64 + cg*4);
            float a[8]={a0.x,a0.y,a0.z,a0.w,a1.x,a1.y,a1.z,a1.w};
            float b[4]={b0.x,b0.y,b0.z,b0.w};
            #pragma unroll
            for (int i=0;i<8;i++)
                #pragma unroll
                for (int j=0;j<4;j++) acc[i][j] = fmaf(a[i], b[j], acc[i][j]);
        }
        __syncthreads();
    }
    float4 bb0 = *(const float4*)(Bias + cg*4);
    float bb[4]={bb0.x,bb0.y,bb0.z,bb0.w};
    #pragma unroll
    for (int i=0;i<8;i++){
        int m = m0 + ((i<4)? rg*4+i : 64+rg*4+(i-4));
        if (m >= M) continue;
        float o[4];
        #pragma unroll
        for (int j=0;j<4;j++){
            float t = acc[i][j]+bb[j];
            o[j] = relu? fmaxf(t,0.f) : t;
        }
        *(float4*)(Y + (size_t)m*64 + cg*4) = make_float4(o[0],o[1],o[2],o[3]);
    }
}

// ---------------- per-round kernels ----------------
__global__ void k_clause_cval(const int* __restrict__ elit, const float* __restrict__ wsig){
    int gw = (blockIdx.x*blockDim.x + threadIdx.x)>>5;
    int lane = threadIdx.x & 31;
    if (gw >= NC) return;
    int c = gw;
    float w = wsig[c];
    float2 acc = {0.f,0.f};
    #pragma unroll
    for (int j=0;j<3;j++){
        int l = elit[3*c+j];
        int v = (l<NV)? l : l-NV;
        float sgn = (l<NV)? 1.f : -1.f;
        float2 q = *(const float2*)(d_query + (size_t)v*64 + lane*2);
        acc.x += sp_f(sgn*q.x);
        acc.y += sp_f(sgn*q.y);
    }
    float2 cl = { expf(-w*acc.x), expf(-w*acc.y) };
    *(float2*)(d_closs + (size_t)c*64 + lane*2) = cl;
}

__global__ void k_var_grad(const float* __restrict__ wsig){
    int gw = (blockIdx.x*blockDim.x + threadIdx.x)>>5;
    int lane = threadIdx.x & 31;
    if (gw >= NV) return;
    int v = gw;
    float2 ap={0.f,0.f}, an={0.f,0.f};
    int s0=d_csroff[v], e0=d_csroff[v+1];
    for (int i=s0;i<e0;i++){
        int c = d_csredge[i]/3;
        float w=wsig[c];
        float2 cl=*(const float2*)(d_closs+(size_t)c*64+lane*2);
        ap.x += w*cl.x; ap.y += w*cl.y;
    }
    int s1=d_csroff[NV+v], e1=d_csroff[NV+v+1];
    for (int i=s1;i<e1;i++){
        int c = d_csredge[i]/3;
        float w=wsig[c];
        float2 cl=*(const float2*)(d_closs+(size_t)c*64+lane*2);
        an.x += w*cl.x; an.y += w*cl.y;
    }
    float2 q = *(const float2*)(d_query + (size_t)v*64 + lane*2);
    float vd = d_vdw[v];
    float2 g;
    g.x = (-ap.x*sigm(q.x) + an.x*sigm(-q.x)) * vd;
    g.y = (-ap.y*sigm(q.y) + an.y*sigm(-q.y)) * vd;
    *(float2*)(d_unit + (size_t)v*256 + lane*2) = g;
    float2 vv = *(const float2*)(d_variables + (size_t)v*64 + lane*2);
    *(float2*)(d_unit + (size_t)v*256 + 64 + lane*2) = vv;
}

// ---------------- pair_norm stats (one pass; Σw = 1 per graph) ----------------
__global__ void k_pn_stats(int mode){
    const float* x; const float* w; const int* st; int stride;
    if (mode==0){ x=d_cdata+64; w=d_cg_norm; st=d_cstart; stride=128; }
    else        { x=d_uout;    w=d_vg_norm; st=d_vstart; stride=64;  }
    int g=blockIdx.x;
    int s=st[g], e=st[g+1];
    int f=threadIdx.x&63, grp=threadIdx.x>>6;
    float s1=0.f, s2=0.f;
    for (int r=s+grp; r<e; r+=4){
        float wr = w[r];
        float xv = x[(size_t)r*stride+f];
        float wx = wr*xv;
        s1 += wx; s2 += wx*xv;
    }
    __shared__ float r1[256], r2[256];
    r1[threadIdx.x]=s1; r2[threadIdx.x]=s2; __syncthreads();
    if (threadIdx.x<64){
        float S1 = r1[f]+r1[64+f]+r1[128+f]+r1[192+f];
        float S2 = r2[f]+r2[64+f]+r2[128+f]+r2[192+f];
        d_mean[g*64+f]=S1;
        r1[f] = S2 - S1*S1;
    }
    __syncthreads();
    if (threadIdx.x<32){
        float v = r1[threadIdx.x]+r1[threadIdx.x+32];
        for (int o=16;o;o>>=1) v += __shfl_down_sync(0xffffffffu, v, o);
        if (threadIdx.x==0) d_varred[g]=v*(1.f/64.f);
    }
}

__global__ void k_pn_apply(int mode, const int* __restrict__ gid, int M){
    if (d_done) return;
    int i = blockIdx.x*blockDim.x + threadIdx.x;
    if (i >= M*64) return;
    int r = i>>6, f = i&63;
    const float* x; float* state; int stride;
    if (mode==0){ x=d_cdata+64; state=d_clause_state; stride=128; }
    else        { x=d_uout;    state=d_variables;    stride=64;  }
    int g = gid[r];
    float xc = x[(size_t)r*stride+f] - d_mean[g*64+f];
    float nrm = xc * rsqrtf(d_varred[g]+1e-6f) * 0.25f;
    state[i] = nrm + 0.1f*state[i];
}

__global__ void k_var_loss(const float* __restrict__ wsig){
    int gw = (blockIdx.x*blockDim.x + threadIdx.x)>>5;
    int lane = threadIdx.x & 31;
    if (gw >= NV) return;
    int v = gw;
    float2 ap={0.f,0.f}, an={0.f,0.f};
    int s0=d_csroff[v], e0=d_csroff[v+1];
    for (int i=s0;i<e0;i++){
        int c = d_csredge[i]/3;
        float w=wsig[c];
        float2 cl=*(const float2*)(d_cdata+(size_t)c*128+lane*2);
        ap.x += w*cl.x; ap.y += w*cl.y;
    }
    int s1=d_csroff[NV+v], e1=d_csroff[NV+v+1];
    for (int i=s1;i<e1;i++){
        int c = d_csredge[i]/3;
        float w=wsig[c];
        float2 cl=*(const float2*)(d_cdata+(size_t)c*128+lane*2);
        an.x += w*cl.x; an.y += w*cl.y;
    }
    float dp = d_degw[v], dn = d_degw[NV+v];
    *(float2*)(d_unit + (size_t)v*256 + 128 + lane*2) = make_float2(ap.x*dp, ap.y*dp);
    *(float2*)(d_unit + (size_t)v*256 + 192 + lane*2) = make_float2(an.x*dn, an.y*dn);
}

__global__ void k_logits(const float* __restrict__ ow2, const float* __restrict__ ob2){
    if (blockIdx.x==0 && threadIdx.x==0) d_allsat = 1;
    int gw = (blockIdx.x*blockDim.x + threadIdx.x)>>5;
    int lane = threadIdx.x & 31;
    if (gw >= NV) return;
    float a=0.f;
    for (int f=lane; f<64; f+=32) a += d_ho[(size_t)gw*64+f]*ow2[f];
    for (int o=16;o;o>>=1) a += __shfl_down_sync(0xffffffffu, a, o);
    if (lane==0){
        float lg = a + ob2[0];
        d_logits[gw] = lg;
        if (!d_done) d_last_logits[gw] = lg;
    }
}

__global__ void k_final_clause(const int* __restrict__ elit, const float* __restrict__ wsig){
    int g = blockIdx.x;
    int s = d_cstart[g], e = d_cstart[g+1];
    float lsum=0.f; int sat=1;
    for (int c=s+threadIdx.x; c<e; c+=blockDim.x){
        float w = wsig[c];
        float cvs=0.f, csat=0.f;
        #pragma unroll
        for (int j=0;j<3;j++){
            int l = elit[3*c+j];
            int v = (l<NV)? l : l-NV;
            float sgn = (l<NV)? 1.f : -1.f;
            float lg = d_logits[v];
            cvs += sp_f(sgn*lg);
            float a = (lg>0.f)? 1.f : 0.f;
            float lit01 = (l<NV)? a : 1.f-a;
            csat += w*lit01;
        }
        float cv = expf(-w*cvs);
        float pc = cv * (-logf(1.f - cv + 1e-10f));
        lsum += pc*w;
        if (csat < 1.f) sat = 0;
    }
    __shared__ float sred[256];
    __shared__ int ssat[256];
    sred[threadIdx.x]=lsum; ssat[threadIdx.x]=sat; __syncthreads();
    for (int o=128;o;o>>=1){
        if (threadIdx.x<o){ sred[threadIdx.x]+=sred[threadIdx.x+o]; ssat[threadIdx.x]&=ssat[threadIdx.x+o]; }
        __syncthreads();
    }
    if (threadIdx.x==0){
        d_pg[g]=sred[0];
        if (!ssat[0]) d_allsat = 0;
    }
}

__global__ void k_finish(){
    int done0 = d_done;
    if (!done0){
        for (int g=threadIdx.x; g<NG; g+=blockDim.x)
            d_loss_sum[g] += sqrtf(d_pg[g]+1e-6f) - 0.001f;
    }
    __syncthreads();
    if (threadIdx.x==0 && !done0){
        d_step++;
        if (d_allsat) d_done = 1;
    }
}

__global__ void k_output(float* __restrict__ out, int n){
    int i = blockIdx.x*blockDim.x + threadIdx.x;
    if (i >= n) return;
    float v;
    if (i < NV)            v = d_last_logits[i];
    else if (i < NV+NG)    v = d_loss_sum[i-NV]*(1.f/(float)RNDS);
    else if (i == NV+NG)   v = (float)d_step;
    else                   v = 0.f;
    out[i] = v;
}

// ---------------- host ----------------
extern "C" void kernel_launch(void* const* d_in, const int* in_sizes, int n_in,
                              void* d_out, int out_size){
    const float* wsig   = (const float*)d_in[0];
    const float* wsp    = (const float*)d_in[1];
    const float* noise  = (const float*)d_in[2];
    const int*   elit   = (const int*)d_in[3];
    const int*   eclause= (const int*)d_in[4];
    const int*   cgid   = (const int*)d_in[5];
    const int*   vgid   = (const int*)d_in[6];
    const float* P[18];
    for (int i=0;i<18;i++) P[i]=(const float*)d_in[7+i];
    const float *qw1=P[0],*qb1=P[1],*qw2=P[2],*qb2=P[3];
    const float *cw1=P[4],*cb1=P[5],*cw2=P[6],*cb2=P[7];
    const float *uw1=P[8],*ub1=P[9],*uw2=P[10],*ub2=P[11],*uw3=P[12],*ub3=P[13];
    const float *ow1=P[14],*ob1=P[15],*ow2=P[16],*ob2=P[17];

    float *p_hq,*p_query,*p_hc,*p_cdata,*p_unit,*p_hu1,*p_hu2,*p_uout,*p_vars,*p_cs,*p_closs,*p_ho;
    cudaGetSymbolAddress((void**)&p_hq,    d_hq);
    cudaGetSymbolAddress((void**)&p_query, d_query);
    cudaGetSymbolAddress((void**)&p_hc,    d_hc);
    cudaGetSymbolAddress((void**)&p_cdata, d_cdata);
    cudaGetSymbolAddress((void**)&p_unit,  d_unit);
    cudaGetSymbolAddress((void**)&p_hu1,   d_hu1);
    cudaGetSymbolAddress((void**)&p_hu2,   d_hu2);
    cudaGetSymbolAddress((void**)&p_uout,  d_uout);
    cudaGetSymbolAddress((void**)&p_vars,  d_variables);
    cudaGetSymbolAddress((void**)&p_cs,    d_clause_state);
    cudaGetSymbolAddress((void**)&p_closs, d_closs);
    cudaGetSymbolAddress((void**)&p_ho,    d_ho);

    const int GV = CEILDIV(NV,BM);   // 157
    const int GC = CEILDIV(NC,BM);   // 657

    // ---- init / precompute ----
    k_init<<<CEILDIV(2*NV,256),256>>>();
    k_init_state<<<CEILDIV(NC*64,256),256>>>();
    k_edge_scatter<<<CEILDIV(NE,256),256>>>(elit, eclause, wsig, wsp);
    k_scan<<<1,1024>>>();
    k_fill<<<CEILDIV(NE,256),256>>>(elit);
    k_segmin<<<CEILDIV(NC,256),256>>>(cgid, vgid);
    k_segfix<<<1,32>>>();
    k_var_pre<<<CEILDIV(NV,256),256>>>(vgid);
    k_clause_pre<<<CEILDIV(NC,256),256>>>(cgid, wsig);
    k_norms<<<CEILDIV(NC,256),256>>>(cgid, vgid, wsig);

    // ---- rounds ----
    for (int t=0; t<RNDS; t++){
        const float* nt = noise + (size_t)t*NV*4;
        // q-MLP: v1 = [variables | noise] (K=68, padded 80)
        k_gemm_n64<<<GV,256>>>(p_vars, nt, 1.f, 64, 4, qw1, qb1, p_hq, NV, 80, 68, 1);
        k_gemm_n64<<<GV,256>>>(p_hq, nullptr, 0.f, 64, 0, qw2, qb2, p_query, NV, 64, 64, 0);
        k_clause_cval<<<CEILDIV(NC*32,256),256>>>(elit, wsig);
        k_var_grad<<<CEILDIV(NV*32,256),256>>>(wsig);
        // c-MLP: cu = [clause_state | 4*closs]
        k_gemm_n128<<<GC,256>>>(p_cs, p_closs, 4.f, 64, 64, cw1, cb1, p_hc, NC, 128, 128, 1);
        k_gemm_n128<<<GC,256>>>(p_hc, nullptr, 0.f, 128, 0, cw2, cb2, p_cdata, NC, 128, 128, 0);
        k_pn_stats<<<NG,256>>>(0);
        k_pn_apply<<<CEILDIV(NC*64,256),256>>>(0, cgid, NC);
        k_var_loss<<<CEILDIV(NV*32,256),256>>>(wsig);
        // u-MLP
        k_gemm_n128<<<GV,256>>>(p_unit, nullptr, 0.f, 256, 0, uw1, ub1, p_hu1, NV, 256, 256, 1);
        k_gemm_n128<<<GV,256>>>(p_hu1, nullptr, 0.f, 128, 0, uw2, ub2, p_hu2, NV, 128, 128, 1);
        k_gemm_n64 <<<GV,256>>>(p_hu2, nullptr, 0.f, 128, 0, uw3, ub3, p_uout, NV, 128, 128, 0);
        k_pn_stats<<<NG,256>>>(1);
        k_pn_apply<<<CEILDIV(NV*64,256),256>>>(1, vgid, NV);
        // o-MLP
        k_gemm_n64<<<GV,256>>>(p_vars, nullptr, 0.f, 64, 0, ow1, ob1, p_ho, NV, 64, 64, 1);
        k_logits<<<CEILDIV(NV*32,256),256>>>(ow2, ob2);
        k_final_clause<<<NG,256>>>(elit, wsig);
        k_finish<<<1,256>>>();
    }

    k_output<<<CEILDIV(out_size>0?out_size:1,256),256>>>((float*)d_out, out_size);
}

// round 4
// speedup vs baseline: 1.9622x; 1.0258x over previous
#include <cuda_runtime.h>
#include <cstdint>

#define NV 20000
#define NC 84000
#define NG 200
#define NE 252000
#define RNDS 8
#define CEILDIV(a,b) (((a)+(b)-1)/(b))

// ---------------- scratch (device globals; allocated at module load) ----------------
__device__ __align__(16) float d_variables[NV*64];
__device__ __align__(16) float d_clause_state[NC*64];
__device__ __align__(16) float d_hq[NV*64];
__device__ __align__(16) float d_query[NV*64];
__device__ __align__(16) float d_closs[NC*64];
__device__ __align__(16) float d_hc[NC*128];
__device__ __align__(16) float d_cdata[NC*128];
__device__ __align__(16) float d_unit[NV*256];
__device__ __align__(16) float d_hu1[NV*128];
__device__ __align__(16) float d_hu2[NV*128];
__device__ __align__(16) float d_uout[NV*64];
__device__ __align__(16) float d_ho[NV*64];
__device__ float d_logits[NV];
__device__ float d_last_logits[NV];

__device__ float d_var_sum[2*NV];
__device__ float d_lit_deg[2*NV];
__device__ float d_degw[2*NV];
__device__ float d_vdw[NV];
__device__ float d_vmask[NV];
__device__ float d_vg_norm[NV];
__device__ float d_cg_norm[NC];
__device__ float d_vmask_gsum[NG];
__device__ float d_wsig_gsum[NG];
__device__ float d_loss_sum[NG];
__device__ float d_pg[NG];
__device__ float d_mean[NG*64];
__device__ float d_varred[NG];

__device__ int d_counts[2*NV];
__device__ int d_csroff[2*NV+1];
__device__ int d_cursor[2*NV];
__device__ int d_csrclause[NE];
__device__ int d_cstart[NG+1];
__device__ int d_vstart[NG+1];
__device__ int d_done;
__device__ int d_allsat;
__device__ int d_step;

// ---------------- helpers ----------------
__device__ __forceinline__ float sp_f(float x){ return fmaxf(x,0.f)+log1pf(expf(-fabsf(x))); }
__device__ __forceinline__ float sigm(float x){ return 1.f/(1.f+expf(-x)); }
__device__ __forceinline__ float tf32_rn(float x){
    uint32_t u; asm("cvt.rna.tf32.f32 %0, %1;" : "=r"(u) : "f"(x));
    return __uint_as_float(u);
}

#define MMA_TF32(c, a, b0, b1) \
  asm volatile("mma.sync.aligned.m16n8k8.row.col.f32.tf32.tf32.f32 " \
    "{%0,%1,%2,%3}, {%4,%5,%6,%7}, {%8,%9}, {%0,%1,%2,%3};" \
    : "+f"((c)[0]), "+f"((c)[1]), "+f"((c)[2]), "+f"((c)[3]) \
    : "r"((a)[0]), "r"((a)[1]), "r"((a)[2]), "r"((a)[3]), "r"(b0), "r"(b1))

// ---------------- init ----------------
__global__ void k_init(){
    int i = blockIdx.x*blockDim.x + threadIdx.x;
    if (i < 2*NV){ d_var_sum[i]=0.f; d_lit_deg[i]=0.f; d_counts[i]=0; d_cursor[i]=0; }
    if (i < NG){ d_vmask_gsum[i]=0.f; d_wsig_gsum[i]=0.f; d_loss_sum[i]=0.f; }
    if (i <= NG){ d_cstart[i]=NC; d_vstart[i]=NV; }
    if (i == 0){ d_done=0; d_allsat=1; d_step=0; d_csroff[2*NV]=NE; }
}

__global__ void k_init_state(){
    int i = blockIdx.x*blockDim.x + threadIdx.x;
    if (i < NC*64) d_clause_state[i]=1.f;
    if (i < NV*64) d_variables[i]=1.f;
}

__global__ void k_edge_scatter(const int* __restrict__ elit, const int* __restrict__ eclause,
                               const float* __restrict__ wsig, const float* __restrict__ wsp){
    int e = blockIdx.x*blockDim.x + threadIdx.x;
    if (e >= NE) return;
    int c = eclause[e];
    int l = elit[e];
    float w = wsig[c];
    atomicAdd(&d_var_sum[l], w*wsp[c]);
    atomicAdd(&d_lit_deg[l], w);
    atomicAdd(&d_counts[l], 1);
}

__global__ void k_scan(){
    __shared__ int sh[1024];
    int tid = threadIdx.x;
    const int PER = 40;
    int base = tid*PER;
    int sum = 0;
    for (int i=base; i<base+PER && i<2*NV; i++) sum += d_counts[i];
    sh[tid]=sum; __syncthreads();
    for (int off=1; off<1024; off<<=1){
        int t = (tid>=off)? sh[tid-off] : 0;
        __syncthreads();
        sh[tid]+=t;
        __syncthreads();
    }
    int run = sh[tid]-sum;
    for (int i=base; i<base+PER && i<2*NV; i++){ d_csroff[i]=run; run+=d_counts[i]; }
}

__global__ void k_fill(const int* __restrict__ elit){
    int e = blockIdx.x*blockDim.x + threadIdx.x;
    if (e >= NE) return;
    int l = elit[e];
    int p = atomicAdd(&d_cursor[l], 1);
    d_csrclause[d_csroff[l]+p] = e/3;
}

__global__ void k_segmin(const int* __restrict__ cgid, const int* __restrict__ vgid){
    int i = blockIdx.x*blockDim.x + threadIdx.x;
    if (i < NC) atomicMin(&d_cstart[cgid[i]], i);
    if (i < NV) atomicMin(&d_vstart[vgid[i]], i);
}

__global__ void k_segfix(){
    if (threadIdx.x==0){
        d_cstart[NG]=NC;
        for (int g=NG-1; g>=0; g--) d_cstart[g]=min(d_cstart[g], d_cstart[g+1]);
    }
    if (threadIdx.x==1){
        d_vstart[NG]=NV;
        for (int g=NG-1; g>=0; g--) d_vstart[g]=min(d_vstart[g], d_vstart[g+1]);
    }
}

__global__ void k_var_pre(const int* __restrict__ vgid){
    int v = blockIdx.x*blockDim.x + threadIdx.x;
    if (v >= NV) return;
    float m = 1.f - expf(-(d_var_sum[v] + d_var_sum[v+NV]));
    d_vmask[v] = m;
    atomicAdd(&d_vmask_gsum[vgid[v]], m);
    float dp = d_lit_deg[v], dn = d_lit_deg[v+NV];
    d_degw[v]    = rsqrtf(fmaxf(dp,1.f));
    d_degw[v+NV] = rsqrtf(fmaxf(dn,1.f));
    d_vdw[v]     = 4.f*rsqrtf(fmaxf(dp+dn,1.f));
}

__global__ void k_clause_pre(const int* __restrict__ cgid, const float* __restrict__ wsig){
    int c = blockIdx.x*blockDim.x + threadIdx.x;
    if (c >= NC) return;
    atomicAdd(&d_wsig_gsum[cgid[c]], wsig[c]);
}

__global__ void k_norms(const int* __restrict__ cgid, const int* __restrict__ vgid,
                        const float* __restrict__ wsig){
    int i = blockIdx.x*blockDim.x + threadIdx.x;
    if (i < NC){
        float s = d_wsig_gsum[cgid[i]];
        d_cg_norm[i] = wsig[i] * (s>0.f ? 1.f/s : 0.f);
    }
    if (i < NV){
        float s = d_vmask_gsum[vgid[i]];
        d_vg_norm[i] = d_vmask[i] * (s>0.f ? 1.f/s : 0.f);
    }
}

// ============== 3xTF32 tensor-core GEMM ==============
// Y[M,N] = act(concat(X1[K1], scale2*X2[K2], 0-pad)[M,Kp] @ W[Ktrue,N] + B)
// BM=128, BK=16, 256 threads. A/B staged hi/lo in smem (stride 136 => conflict-free frags).

#define ASTR 136

__global__ void __launch_bounds__(256,2)
k_gemm_tf32_n128(const float* __restrict__ X1, const float* __restrict__ X2, float scale2,
                 int K1, int K2,
                 const float* __restrict__ W, const float* __restrict__ Bias,
                 float* __restrict__ Y, int M, int Kp, int Ktrue, int relu)
{
    __shared__ float Ah[16*ASTR], Al[16*ASTR], Bh[16*ASTR], Bl[16*ASTR];
    int tid = threadIdx.x;
    int lane = tid & 31, wid = tid >> 5;
    int warp_m = wid >> 1, warp_n = wid & 1;
    int g = lane >> 2, tig = lane & 3;
    int m0 = blockIdx.x * 128;

    float acc[2][8][4];
    #pragma unroll
    for (int a=0;a<2;a++)
        #pragma unroll
        for (int b=0;b<8;b++)
            #pragma unroll
            for (int cc=0;cc<4;cc++) acc[a][b][cc]=0.f;

    for (int k0=0; k0<Kp; k0+=16){
        // stage A (transposed [k][m], hi/lo)
        {
            int q = tid & 3;
            int mrow = tid >> 2;
            #pragma unroll
            for (int h=0; h<2; h++){
                int m = mrow + h*64;
                int gm = m0 + m;
                int c = k0 + q*4;
                float4 v = {0.f,0.f,0.f,0.f};
                if (gm < M){
                    if (c < K1) v = *(const float4*)(X1 + (size_t)gm*K1 + c);
                    else if (K2 && c < K1+K2){
                        v = *(const float4*)(X2 + (size_t)gm*K2 + (c-K1));
                        v.x*=scale2; v.y*=scale2; v.z*=scale2; v.w*=scale2;
                    }
                }
                float xs[4]={v.x,v.y,v.z,v.w};
                #pragma unroll
                for (int j=0;j<4;j++){
                    float hi = tf32_rn(xs[j]);
                    Ah[(q*4+j)*ASTR + m] = hi;
                    Al[(q*4+j)*ASTR + m] = tf32_rn(xs[j]-hi);
                }
            }
        }
        // stage B [k][n], hi/lo
        {
            int kr = tid >> 5;
            #pragma unroll
            for (int h=0; h<2; h++){
                int k = kr + h*8;
                float4 v = {0.f,0.f,0.f,0.f};
                if (k0 + k < Ktrue) v = *(const float4*)(W + (size_t)(k0+k)*128 + lane*4);
                float xs[4]={v.x,v.y,v.z,v.w};
                #pragma unroll
                for (int j=0;j<4;j++){
                    float hi = tf32_rn(xs[j]);
                    Bh[k*ASTR + lane*4 + j] = hi;
                    Bl[k*ASTR + lane*4 + j] = tf32_rn(xs[j]-hi);
                }
            }
        }
        __syncthreads();
        #pragma unroll
        for (int ks=0; ks<16; ks+=8){
            uint32_t ah[2][4], al[2][4];
            #pragma unroll
            for (int mt=0; mt<2; mt++){
                int mb = warp_m*32 + mt*16 + g;
                int r0 = (ks+tig)*ASTR + mb;
                int r1 = (ks+tig+4)*ASTR + mb;
                ah[mt][0]=__float_as_uint(Ah[r0]);   ah[mt][1]=__float_as_uint(Ah[r0+8]);
                ah[mt][2]=__float_as_uint(Ah[r1]);   ah[mt][3]=__float_as_uint(Ah[r1+8]);
                al[mt][0]=__float_as_uint(Al[r0]);   al[mt][1]=__float_as_uint(Al[r0+8]);
                al[mt][2]=__float_as_uint(Al[r1]);   al[mt][3]=__float_as_uint(Al[r1+8]);
            }
            #pragma unroll
            for (int nt=0; nt<8; nt++){
                int n = warp_n*64 + nt*8 + g;
                int i0=(ks+tig)*ASTR+n, i1=(ks+tig+4)*ASTR+n;
                uint32_t bh0=__float_as_uint(Bh[i0]), bh1=__float_as_uint(Bh[i1]);
                uint32_t bl0=__float_as_uint(Bl[i0]), bl1=__float_as_uint(Bl[i1]);
                #pragma unroll
                for (int mt=0; mt<2; mt++){
                    MMA_TF32(acc[mt][nt], ah[mt], bh0, bh1);
                    MMA_TF32(acc[mt][nt], ah[mt], bl0, bl1);
                    MMA_TF32(acc[mt][nt], al[mt], bh0, bh1);
                }
            }
        }
        __syncthreads();
    }
    // epilogue
    #pragma unroll
    for (int mt=0; mt<2; mt++){
        int rm0 = m0 + warp_m*32 + mt*16 + g;
        int rm1 = rm0 + 8;
        #pragma unroll
        for (int nt=0; nt<8; nt++){
            int col = warp_n*64 + nt*8 + 2*tig;
            float bb0 = __ldg(Bias+col), bb1 = __ldg(Bias+col+1);
            float o0=acc[mt][nt][0]+bb0, o1=acc[mt][nt][1]+bb1;
            float o2=acc[mt][nt][2]+bb0, o3=acc[mt][nt][3]+bb1;
            if (relu){ o0=fmaxf(o0,0.f); o1=fmaxf(o1,0.f); o2=fmaxf(o2,0.f); o3=fmaxf(o3,0.f); }
            if (rm0 < M) *(float2*)(Y + (size_t)rm0*128 + col) = make_float2(o0,o1);
            if (rm1 < M) *(float2*)(Y + (size_t)rm1*128 + col) = make_float2(o2,o3);
        }
    }
}

#define BSTR 72

__global__ void __launch_bounds__(256,2)
k_gemm_tf32_n64(const float* __restrict__ X1, const float* __restrict__ X2, float scale2,
                int K1, int K2,
                const float* __restrict__ W, const float* __restrict__ Bias,
                float* __restrict__ Y, int M, int Kp, int Ktrue, int relu)
{
    __shared__ float Ah[16*ASTR], Al[16*ASTR], Bh[16*BSTR], Bl[16*BSTR];
    int tid = threadIdx.x;
    int lane = tid & 31, wid = tid >> 5;
    int g = lane >> 2, tig = lane & 3;
    int m0 = blockIdx.x * 128;

    float acc[8][4];
    #pragma unroll
    for (int b=0;b<8;b++)
        #pragma unroll
        for (int cc=0;cc<4;cc++) acc[b][cc]=0.f;

    for (int k0=0; k0<Kp; k0+=16){
        {
            int q = tid & 3;
            int mrow = tid >> 2;
            #pragma unroll
            for (int h=0; h<2; h++){
                int m = mrow + h*64;
                int gm = m0 + m;
                int c = k0 + q*4;
                float4 v = {0.f,0.f,0.f,0.f};
                if (gm < M){
                    if (c < K1) v = *(const float4*)(X1 + (size_t)gm*K1 + c);
                    else if (K2 && c < K1+K2){
                        v = *(const float4*)(X2 + (size_t)gm*K2 + (c-K1));
                        v.x*=scale2; v.y*=scale2; v.z*=scale2; v.w*=scale2;
                    }
                }
                float xs[4]={v.x,v.y,v.z,v.w};
                #pragma unroll
                for (int j=0;j<4;j++){
                    float hi = tf32_rn(xs[j]);
                    Ah[(q*4+j)*ASTR + m] = hi;
                    Al[(q*4+j)*ASTR + m] = tf32_rn(xs[j]-hi);
                }
            }
        }
        {
            int kr = tid >> 4, quad = tid & 15;
            float4 v = {0.f,0.f,0.f,0.f};
            if (k0 + kr < Ktrue) v = *(const float4*)(W + (size_t)(k0+kr)*64 + quad*4);
            float xs[4]={v.x,v.y,v.z,v.w};
            #pragma unroll
            for (int j=0;j<4;j++){
                float hi = tf32_rn(xs[j]);
                Bh[kr*BSTR + quad*4 + j] = hi;
                Bl[kr*BSTR + quad*4 + j] = tf32_rn(xs[j]-hi);
            }
        }
        __syncthreads();
        #pragma unroll
        for (int ks=0; ks<16; ks+=8){
            uint32_t ah[4], al[4];
            {
                int mb = wid*16 + g;
                int r0 = (ks+tig)*ASTR + mb;
                int r1 = (ks+tig+4)*ASTR + mb;
                ah[0]=__float_as_uint(Ah[r0]);   ah[1]=__float_as_uint(Ah[r0+8]);
                ah[2]=__float_as_uint(Ah[r1]);   ah[3]=__float_as_uint(Ah[r1+8]);
                al[0]=__float_as_uint(Al[r0]);   al[1]=__float_as_uint(Al[r0+8]);
                al[2]=__float_as_uint(Al[r1]);   al[3]=__float_as_uint(Al[r1+8]);
            }
            #pragma unroll
            for (int nt=0; nt<8; nt++){
                int n = nt*8 + g;
                int i0=(ks+tig)*BSTR+n, i1=(ks+tig+4)*BSTR+n;
                uint32_t bh0=__float_as_uint(Bh[i0]), bh1=__float_as_uint(Bh[i1]);
                uint32_t bl0=__float_as_uint(Bl[i0]), bl1=__float_as_uint(Bl[i1]);
                MMA_TF32(acc[nt], ah, bh0, bh1);
                MMA_TF32(acc[nt], ah, bl0, bl1);
                MMA_TF32(acc[nt], al, bh0, bh1);
            }
        }
        __syncthreads();
    }
    int rm0 = m0 + wid*16 + g;
    int rm1 = rm0 + 8;
    #pragma unroll
    for (int nt=0; nt<8; nt++){
        int col = nt*8 + 2*tig;
        float bb0 = __ldg(Bias+col), bb1 = __ldg(Bias+col+1);
        float o0=acc[nt][0]+bb0, o1=acc[nt][1]+bb1;
        float o2=acc[nt][2]+bb0, o3=acc[nt][3]+bb1;
        if (relu){ o0=fmaxf(o0,0.f); o1=fmaxf(o1,0.f); o2=fmaxf(o2,0.f); o3=fmaxf(o3,0.f); }
        if (rm0 < M) *(float2*)(Y + (size_t)rm0*64 + col) = make_float2(o0,o1);
        if (rm1 < M) *(float2*)(Y + (size_t)rm1*64 + col) = make_float2(o2,o3);
    }
}

// ---------------- per-round kernels ----------------
__global__ void k_clause_cval(const int* __restrict__ elit, const float* __restrict__ wsig){
    int gw = (blockIdx.x*blockDim.x + threadIdx.x)>>5;
    int lane = threadIdx.x & 31;
    if (gw >= NC) return;
    int c = gw;
    float w = wsig[c];
    float2 acc = {0.f,0.f};
    #pragma unroll
    for (int j=0;j<3;j++){
        int l = elit[3*c+j];
        int v = (l<NV)? l : l-NV;
        float sgn = (l<NV)? 1.f : -1.f;
        float2 q = *(const float2*)(d_query + (size_t)v*64 + lane*2);
        acc.x += sp_f(sgn*q.x);
        acc.y += sp_f(sgn*q.y);
    }
    float2 cl = { expf(-w*acc.x), expf(-w*acc.y) };
    *(float2*)(d_closs + (size_t)c*64 + lane*2) = cl;
}

__global__ void k_var_grad(const float* __restrict__ wsig){
    int gw = (blockIdx.x*blockDim.x + threadIdx.x)>>5;
    int lane = threadIdx.x & 31;
    if (gw >= NV) return;
    int v = gw;
    float2 ap={0.f,0.f}, an={0.f,0.f};
    int s0=d_csroff[v], e0=d_csroff[v+1];
    for (int i=s0;i<e0;i++){
        int c = d_csrclause[i];
        float w=wsig[c];
        float2 cl=*(const float2*)(d_closs+(size_t)c*64+lane*2);
        ap.x += w*cl.x; ap.y += w*cl.y;
    }
    int s1=d_csroff[NV+v], e1=d_csroff[NV+v+1];
    for (int i=s1;i<e1;i++){
        int c = d_csrclause[i];
        float w=wsig[c];
        float2 cl=*(const float2*)(d_closs+(size_t)c*64+lane*2);
        an.x += w*cl.x; an.y += w*cl.y;
    }
    float2 q = *(const float2*)(d_query + (size_t)v*64 + lane*2);
    float vd = d_vdw[v];
    float2 gg;
    gg.x = (-ap.x*sigm(q.x) + an.x*sigm(-q.x)) * vd;
    gg.y = (-ap.y*sigm(q.y) + an.y*sigm(-q.y)) * vd;
    *(float2*)(d_unit + (size_t)v*256 + lane*2) = gg;
    float2 vv = *(const float2*)(d_variables + (size_t)v*64 + lane*2);
    *(float2*)(d_unit + (size_t)v*256 + 64 + lane*2) = vv;
}

// ---------------- pair_norm stats (one pass; Σw = 1 per graph) ----------------
__global__ void k_pn_stats(int mode){
    const float* x; const float* w; const int* st; int stride;
    if (mode==0){ x=d_cdata+64; w=d_cg_norm; st=d_cstart; stride=128; }
    else        { x=d_uout;    w=d_vg_norm; st=d_vstart; stride=64;  }
    int g=blockIdx.x;
    int s=st[g], e=st[g+1];
    int f=threadIdx.x&63, grp=threadIdx.x>>6;
    float s1=0.f, s2=0.f;
    for (int r=s+grp; r<e; r+=4){
        float wr = w[r];
        float xv = x[(size_t)r*stride+f];
        float wx = wr*xv;
        s1 += wx; s2 += wx*xv;
    }
    __shared__ float r1[256], r2[256];
    r1[threadIdx.x]=s1; r2[threadIdx.x]=s2; __syncthreads();
    if (threadIdx.x<64){
        float S1 = r1[f]+r1[64+f]+r1[128+f]+r1[192+f];
        float S2 = r2[f]+r2[64+f]+r2[128+f]+r2[192+f];
        d_mean[g*64+f]=S1;
        r1[f] = S2 - S1*S1;
    }
    __syncthreads();
    if (threadIdx.x<32){
        float v = r1[threadIdx.x]+r1[threadIdx.x+32];
        for (int o=16;o;o>>=1) v += __shfl_down_sync(0xffffffffu, v, o);
        if (threadIdx.x==0) d_varred[g]=v*(1.f/64.f);
    }
}

__global__ void k_pn_apply(int mode, const int* __restrict__ gid, int M){
    if (d_done) return;
    int i = blockIdx.x*blockDim.x + threadIdx.x;
    if (i >= M*64) return;
    int r = i>>6, f = i&63;
    const float* x; float* state; int stride;
    if (mode==0){ x=d_cdata+64; state=d_clause_state; stride=128; }
    else        { x=d_uout;    state=d_variables;    stride=64;  }
    int g = gid[r];
    float xc = x[(size_t)r*stride+f] - d_mean[g*64+f];
    float nrm = xc * rsqrtf(d_varred[g]+1e-6f) * 0.25f;
    state[i] = nrm + 0.1f*state[i];
}

__global__ void k_var_loss(const float* __restrict__ wsig){
    int gw = (blockIdx.x*blockDim.x + threadIdx.x)>>5;
    int lane = threadIdx.x & 31;
    if (gw >= NV) return;
    int v = gw;
    float2 ap={0.f,0.f}, an={0.f,0.f};
    int s0=d_csroff[v], e0=d_csroff[v+1];
    for (int i=s0;i<e0;i++){
        int c = d_csrclause[i];
        float w=wsig[c];
        float2 cl=*(const float2*)(d_cdata+(size_t)c*128+lane*2);
        ap.x += w*cl.x; ap.y += w*cl.y;
    }
    int s1=d_csroff[NV+v], e1=d_csroff[NV+v+1];
    for (int i=s1;i<e1;i++){
        int c = d_csrclause[i];
        float w=wsig[c];
        float2 cl=*(const float2*)(d_cdata+(size_t)c*128+lane*2);
        an.x += w*cl.x; an.y += w*cl.y;
    }
    float dp = d_degw[v], dn = d_degw[NV+v];
    *(float2*)(d_unit + (size_t)v*256 + 128 + lane*2) = make_float2(ap.x*dp, ap.y*dp);
    *(float2*)(d_unit + (size_t)v*256 + 192 + lane*2) = make_float2(an.x*dn, an.y*dn);
}

__global__ void k_logits(const float* __restrict__ ow2, const float* __restrict__ ob2){
    if (blockIdx.x==0 && threadIdx.x==0) d_allsat = 1;
    int gw = (blockIdx.x*blockDim.x + threadIdx.x)>>5;
    int lane = threadIdx.x & 31;
    if (gw >= NV) return;
    float a=0.f;
    for (int f=lane; f<64; f+=32) a += d_ho[(size_t)gw*64+f]*ow2[f];
    for (int o=16;o;o>>=1) a += __shfl_down_sync(0xffffffffu, a, o);
    if (lane==0){
        float lg = a + ob2[0];
        d_logits[gw] = lg;
        if (!d_done) d_last_logits[gw] = lg;
    }
}

__global__ void k_final_clause(const int* __restrict__ elit, const float* __restrict__ wsig){
    int g = blockIdx.x;
    int s = d_cstart[g], e = d_cstart[g+1];
    float lsum=0.f; int sat=1;
    for (int c=s+threadIdx.x; c<e; c+=blockDim.x){
        float w = wsig[c];
        float cvs=0.f, csat=0.f;
        #pragma unroll
        for (int j=0;j<3;j++){
            int l = elit[3*c+j];
            int v = (l<NV)? l : l-NV;
            float sgn = (l<NV)? 1.f : -1.f;
            float lg = d_logits[v];
            cvs += sp_f(sgn*lg);
            float a = (lg>0.f)? 1.f : 0.f;
            float lit01 = (l<NV)? a : 1.f-a;
            csat += w*lit01;
        }
        float cv = expf(-w*cvs);
        float pc = cv * (-logf(1.f - cv + 1e-10f));
        lsum += pc*w;
        if (csat < 1.f) sat = 0;
    }
    __shared__ float sred[256];
    __shared__ int ssat[256];
    sred[threadIdx.x]=lsum; ssat[threadIdx.x]=sat; __syncthreads();
    for (int o=128;o;o>>=1){
        if (threadIdx.x<o){ sred[threadIdx.x]+=sred[threadIdx.x+o]; ssat[threadIdx.x]&=ssat[threadIdx.x+o]; }
        __syncthreads();
    }
    if (threadIdx.x==0){
        d_pg[g]=sred[0];
        if (!ssat[0]) d_allsat = 0;
    }
}

__global__ void k_finish(){
    int done0 = d_done;
    if (!done0){
        for (int g=threadIdx.x; g<NG; g+=blockDim.x)
            d_loss_sum[g] += sqrtf(d_pg[g]+1e-6f) - 0.001f;
    }
    __syncthreads();
    if (threadIdx.x==0 && !done0){
        d_step++;
        if (d_allsat) d_done = 1;
    }
}

__global__ void k_output(float* __restrict__ out, int n){
    int i = blockIdx.x*blockDim.x + threadIdx.x;
    if (i >= n) return;
    float v;
    if (i < NV)            v = d_last_logits[i];
    else if (i < NV+NG)    v = d_loss_sum[i-NV]*(1.f/(float)RNDS);
    else if (i == NV+NG)   v = (float)d_step;
    else                   v = 0.f;
    out[i] = v;
}

// ---------------- host ----------------
extern "C" void kernel_launch(void* const* d_in, const int* in_sizes, int n_in,
                              void* d_out, int out_size){
    const float* wsig   = (const float*)d_in[0];
    const float* wsp    = (const float*)d_in[1];
    const float* noise  = (const float*)d_in[2];
    const int*   elit   = (const int*)d_in[3];
    const int*   eclause= (const int*)d_in[4];
    const int*   cgid   = (const int*)d_in[5];
    const int*   vgid   = (const int*)d_in[6];
    const float* P[18];
    for (int i=0;i<18;i++) P[i]=(const float*)d_in[7+i];
    const float *qw1=P[0],*qb1=P[1],*qw2=P[2],*qb2=P[3];
    const float *cw1=P[4],*cb1=P[5],*cw2=P[6],*cb2=P[7];
    const float *uw1=P[8],*ub1=P[9],*uw2=P[10],*ub2=P[11],*uw3=P[12],*ub3=P[13];
    const float *ow1=P[14],*ob1=P[15],*ow2=P[16],*ob2=P[17];

    float *p_hq,*p_query,*p_hc,*p_cdata,*p_unit,*p_hu1,*p_hu2,*p_uout,*p_vars,*p_cs,*p_closs,*p_ho;
    cudaGetSymbolAddress((void**)&p_hq,    d_hq);
    cudaGetSymbolAddress((void**)&p_query, d_query);
    cudaGetSymbolAddress((void**)&p_hc,    d_hc);
    cudaGetSymbolAddress((void**)&p_cdata, d_cdata);
    cudaGetSymbolAddress((void**)&p_unit,  d_unit);
    cudaGetSymbolAddress((void**)&p_hu1,   d_hu1);
    cudaGetSymbolAddress((void**)&p_hu2,   d_hu2);
    cudaGetSymbolAddress((void**)&p_uout,  d_uout);
    cudaGetSymbolAddress((void**)&p_vars,  d_variables);
    cudaGetSymbolAddress((void**)&p_cs,    d_clause_state);
    cudaGetSymbolAddress((void**)&p_closs, d_closs);
    cudaGetSymbolAddress((void**)&p_ho,    d_ho);

    const int GV = CEILDIV(NV,128);   // 157
    const int GC = CEILDIV(NC,128);   // 657

    // ---- init / precompute ----
    k_init<<<CEILDIV(2*NV,256),256>>>();
    k_init_state<<<CEILDIV(NC*64,256),256>>>();
    k_edge_scatter<<<CEILDIV(NE,256),256>>>(elit, eclause, wsig, wsp);
    k_scan<<<1,1024>>>();
    k_fill<<<CEILDIV(NE,256),256>>>(elit);
    k_segmin<<<CEILDIV(NC,256),256>>>(cgid, vgid);
    k_segfix<<<1,32>>>();
    k_var_pre<<<CEILDIV(NV,256),256>>>(vgid);
    k_clause_pre<<<CEILDIV(NC,256),256>>>(cgid, wsig);
    k_norms<<<CEILDIV(NC,256),256>>>(cgid, vgid, wsig);

    // ---- rounds ----
    for (int t=0; t<RNDS; t++){
        const float* nt = noise + (size_t)t*NV*4;
        // q-MLP: [variables | noise] (K=68 -> pad 80)
        k_gemm_tf32_n64<<<GV,256>>>(p_vars, nt, 1.f, 64, 4, qw1, qb1, p_hq, NV, 80, 68, 1);
        k_gemm_tf32_n64<<<GV,256>>>(p_hq, nullptr, 0.f, 64, 0, qw2, qb2, p_query, NV, 64, 64, 0);
        k_clause_cval<<<CEILDIV(NC*32,256),256>>>(elit, wsig);
        k_var_grad<<<CEILDIV(NV*32,256),256>>>(wsig);
        // c-MLP: [clause_state | 4*closs]
        k_gemm_tf32_n128<<<GC,256>>>(p_cs, p_closs, 4.f, 64, 64, cw1, cb1, p_hc, NC, 128, 128, 1);
        k_gemm_tf32_n128<<<GC,256>>>(p_hc, nullptr, 0.f, 128, 0, cw2, cb2, p_cdata, NC, 128, 128, 0);
        k_pn_stats<<<NG,256>>>(0);
        k_pn_apply<<<CEILDIV(NC*64,256),256>>>(0, cgid, NC);
        k_var_loss<<<CEILDIV(NV*32,256),256>>>(wsig);
        // u-MLP
        k_gemm_tf32_n128<<<GV,256>>>(p_unit, nullptr, 0.f, 256, 0, uw1, ub1, p_hu1, NV, 256, 256, 1);
        k_gemm_tf32_n128<<<GV,256>>>(p_hu1, nullptr, 0.f, 128, 0, uw2, ub2, p_hu2, NV, 128, 128, 1);
        k_gemm_tf32_n64 <<<GV,256>>>(p_hu2, nullptr, 0.f, 128, 0, uw3, ub3, p_uout, NV, 128, 128, 0);
        k_pn_stats<<<NG,256>>>(1);
        k_pn_apply<<<CEILDIV(NV*64,256),256>>>(1, vgid, NV);
        // o-MLP
        k_gemm_tf32_n64<<<GV,256>>>(p_vars, nullptr, 0.f, 64, 0, ow1, ob1, p_ho, NV, 64, 64, 1);
        k_logits<<<CEILDIV(NV*32,256),256>>>(ow2, ob2);
        k_final_clause<<<NG,256>>>(elit, wsig);
        k_finish<<<1,256>>>();
    }

    k_output<<<CEILDIV(out_size>0?out_size:1,256),256>>>((float*)d_out, out_size);
}

// round 7
// speedup vs baseline: 2.5437x; 1.2964x over previous
#include <cuda_runtime.h>
#include <cuda_bf16.h>
#include <cstdint>

#define NV 20000
#define NC 84000
#define NG 200
#define NE 252000
#define RNDS 8
#define CEILDIV(a,b) (((a)+(b)-1)/(b))
#define SA 20   // smem row stride in 32-bit words (16 data + 4 pad) -> conflict-free frags

// ---------------- scratch (device globals) ----------------
__device__ __align__(16) float d_variables[NV*64];
__device__ __align__(16) float d_clause_state[NC*64];
__device__ __align__(16) float d_hq[NV*64];
__device__ __align__(16) float d_query[NV*64];
__device__ __align__(16) float d_closs[NC*64];
__device__ __align__(16) float d_hc[NC*128];
__device__ __align__(16) float d_cdata[NC*128];
__device__ __align__(16) float d_unit[NV*256];
__device__ __align__(16) float d_hu1[NV*128];
__device__ __align__(16) float d_hu2[NV*128];
__device__ __align__(16) float d_uout[NV*64];
__device__ float d_logits[NV];
__device__ float d_last_logits[NV];

__device__ __align__(16) uint32_t d_wh[52224];
__device__ __align__(16) uint32_t d_wl[52224];

__device__ float d_var_sum[2*NV];
__device__ float d_lit_deg[2*NV];
__device__ float d_degw[2*NV];
__device__ float d_vdw[NV];
__device__ float d_vmask[NV];
__device__ float d_vg_norm[NV];
__device__ float d_cg_norm[NC];
__device__ float d_vmask_gsum[NG];
__device__ float d_wsig_gsum[NG];
__device__ float d_loss_sum[NG];
__device__ float d_pg[NG];
__device__ float d_mean[NG*64];
__device__ float d_varred[NG];

__device__ int d_counts[2*NV];
__device__ int d_csroff[2*NV+1];
__device__ int d_cursor[2*NV];
__device__ int d_csrclause[NE];
__device__ int d_cstart[NG+1];
__device__ int d_vstart[NG+1];
__device__ int d_done;
__device__ int d_allsat;
__device__ int d_step;

// ---------------- helpers ----------------
__device__ __forceinline__ float sp_f(float x){ return fmaxf(x,0.f)+log1pf(expf(-fabsf(x))); }
__device__ __forceinline__ float sigm(float x){ return 1.f/(1.f+expf(-x)); }

__device__ __forceinline__ void pack2(float x0, float x1, uint32_t* ph, uint32_t* pl){
    __nv_bfloat16 h0 = __float2bfloat16_rn(x0);
    __nv_bfloat16 h1 = __float2bfloat16_rn(x1);
    float r0 = x0 - __bfloat162float(h0);
    float r1 = x1 - __bfloat162float(h1);
    __nv_bfloat16 l0 = __float2bfloat16_rn(r0);
    __nv_bfloat16 l1 = __float2bfloat16_rn(r1);
    *ph = ((uint32_t)__bfloat16_as_ushort(h1)<<16) | __bfloat16_as_ushort(h0);
    *pl = ((uint32_t)__bfloat16_as_ushort(l1)<<16) | __bfloat16_as_ushort(l0);
}

#define MMA_BF16(c, a, b0, b1) \
  asm volatile("mma.sync.aligned.m16n8k16.row.col.f32.bf16.bf16.f32 " \
    "{%0,%1,%2,%3}, {%4,%5,%6,%7}, {%8,%9}, {%0,%1,%2,%3};" \
    : "+f"((c)[0]), "+f"((c)[1]), "+f"((c)[2]), "+f"((c)[3]) \
    : "r"((a)[0]), "r"((a)[1]), "r"((a)[2]), "r"((a)[3]), "r"(b0), "r"(b1))

// ---------------- init / precompute ----------------
__global__ void k_init(){
    int i = blockIdx.x*blockDim.x + threadIdx.x;
    if (i < 2*NV){ d_var_sum[i]=0.f; d_lit_deg[i]=0.f; d_counts[i]=0; d_cursor[i]=0; }
    if (i < NG){ d_vmask_gsum[i]=0.f; d_wsig_gsum[i]=0.f; d_loss_sum[i]=0.f; }
    if (i <= NG){ d_cstart[i]=NC; d_vstart[i]=NV; }
    if (i == 0){ d_done=0; d_allsat=1; d_step=0; d_csroff[2*NV]=NE; }
}

__global__ void k_init_state(){
    int i = blockIdx.x*blockDim.x + threadIdx.x;
    if (i < NC*64) d_clause_state[i]=1.f;
    if (i < NV*64) d_variables[i]=1.f;
}

__global__ void k_edge_scatter(const int* __restrict__ elit, const int* __restrict__ eclause,
                               const float* __restrict__ wsig, const float* __restrict__ wsp){
    int e = blockIdx.x*blockDim.x + threadIdx.x;
    if (e >= NE) return;
    int c = eclause[e];
    int l = elit[e];
    float w = wsig[c];
    atomicAdd(&d_var_sum[l], w*wsp[c]);
    atomicAdd(&d_lit_deg[l], w);
    atomicAdd(&d_counts[l], 1);
}

__global__ void k_scan(){
    __shared__ int sh[1024];
    int tid = threadIdx.x;
    const int PER = 40;
    int base = tid*PER;
    int sum = 0;
    for (int i=base; i<base+PER && i<2*NV; i++) sum += d_counts[i];
    sh[tid]=sum; __syncthreads();
    for (int off=1; off<1024; off<<=1){
        int t = (tid>=off)? sh[tid-off] : 0;
        __syncthreads();
        sh[tid]+=t;
        __syncthreads();
    }
    int run = sh[tid]-sum;
    for (int i=base; i<base+PER && i<2*NV; i++){ d_csroff[i]=run; run+=d_counts[i]; }
}

__global__ void k_fill(const int* __restrict__ elit){
    int e = blockIdx.x*blockDim.x + threadIdx.x;
    if (e >= NE) return;
    int l = elit[e];
    int p = atomicAdd(&d_cursor[l], 1);
    d_csrclause[d_csroff[l]+p] = e/3;
}

__global__ void k_segmin(const int* __restrict__ cgid, const int* __restrict__ vgid){
    int i = blockIdx.x*blockDim.x + threadIdx.x;
    if (i < NC) atomicMin(&d_cstart[cgid[i]], i);
    if (i < NV) atomicMin(&d_vstart[vgid[i]], i);
}

__global__ void k_segfix(){
    if (threadIdx.x==0){
        d_cstart[NG]=NC;
        for (int g=NG-1; g>=0; g--) d_cstart[g]=min(d_cstart[g], d_cstart[g+1]);
    }
    if (threadIdx.x==1){
        d_vstart[NG]=NV;
        for (int g=NG-1; g>=0; g--) d_vstart[g]=min(d_vstart[g], d_vstart[g+1]);
    }
}

__global__ void k_var_pre(const int* __restrict__ vgid){
    int v = blockIdx.x*blockDim.x + threadIdx.x;
    if (v >= NV) return;
    float m = 1.f - expf(-(d_var_sum[v] + d_var_sum[v+NV]));
    d_vmask[v] = m;
    atomicAdd(&d_vmask_gsum[vgid[v]], m);
    float dp = d_lit_deg[v], dn = d_lit_deg[v+NV];
    d_degw[v]    = rsqrtf(fmaxf(dp,1.f));
    d_degw[v+NV] = rsqrtf(fmaxf(dn,1.f));
    d_vdw[v]     = 4.f*rsqrtf(fmaxf(dp+dn,1.f));
}

__global__ void k_clause_pre(const int* __restrict__ cgid, const float* __restrict__ wsig){
    int c = blockIdx.x*blockDim.x + threadIdx.x;
    if (c >= NC) return;
    atomicAdd(&d_wsig_gsum[cgid[c]], wsig[c]);
}

__global__ void k_norms(const int* __restrict__ cgid, const int* __restrict__ vgid,
                        const float* __restrict__ wsig){
    int i = blockIdx.x*blockDim.x + threadIdx.x;
    if (i < NC){
        float s = d_wsig_gsum[cgid[i]];
        d_cg_norm[i] = wsig[i] * (s>0.f ? 1.f/s : 0.f);
    }
    if (i < NV){
        float s = d_vmask_gsum[vgid[i]];
        d_vg_norm[i] = d_vmask[i] * (s>0.f ? 1.f/s : 0.f);
    }
}

// weight pre-pack: W[K,N] fp32 -> Wh/Wl [N][Kp/2] bf16x2 (k-pairs, hi/lo split)
__global__ void k_pack_w(const float* __restrict__ W, int Ktrue, int N, int Kp,
                         uint32_t* __restrict__ Wh, uint32_t* __restrict__ Wl){
    int idx = blockIdx.x*blockDim.x + threadIdx.x;
    int hw = Kp>>1;
    if (idx >= N*hw) return;
    int n = idx/hw, kp = idx-n*hw;
    int k0 = 2*kp;
    float x0 = (k0   < Ktrue)? W[(size_t)k0*N+n]     : 0.f;
    float x1 = (k0+1 < Ktrue)? W[(size_t)(k0+1)*N+n] : 0.f;
    pack2(x0, x1, &Wh[idx], &Wl[idx]);
}

// ============== bf16 3-term split tensor-core GEMMs ==============

__global__ void __launch_bounds__(256,2)
k_gemm_bf16_n128(const float* __restrict__ X1, const float* __restrict__ X2, float scale2,
                 int K1, int K2,
                 const uint32_t* __restrict__ Wh, const uint32_t* __restrict__ Wl,
                 const float* __restrict__ Bias,
                 float* __restrict__ Y, int M, int Kp, int relu)
{
    __shared__ uint32_t Ah[128*SA], Al[128*SA], Bh[128*SA], Bl[128*SA];
    int tid = threadIdx.x, lane = tid&31, wid = tid>>5;
    int warp_m = wid>>1, warp_n = wid&1, g = lane>>2, tig = lane&3;
    int m0 = blockIdx.x*128;
    int hw = Kp>>1;

    float acc[2][8][4];
    #pragma unroll
    for (int a=0;a<2;a++)
        #pragma unroll
        for (int b=0;b<8;b++)
            #pragma unroll
            for (int cc=0;cc<4;cc++) acc[a][b][cc]=0.f;

    int m = tid>>1, q = tid&1, gm = m0+m;
    for (int k0=0; k0<Kp; k0+=32){
        #pragma unroll
        for (int h=0; h<4; h++){
            int c = k0 + (q*4+h)*4;
            float4 v = {0.f,0.f,0.f,0.f};
            if (gm < M){
                if (c < K1) v = *(const float4*)(X1 + (size_t)gm*K1 + c);
                else if (c < K1+K2){
                    v = *(const float4*)(X2 + (size_t)gm*K2 + (c-K1));
                    v.x*=scale2; v.y*=scale2; v.z*=scale2; v.w*=scale2;
                }
            }
            int kp = (q*4+h)*2;
            pack2(v.x,v.y,&Ah[m*SA+kp],  &Al[m*SA+kp]);
            pack2(v.z,v.w,&Ah[m*SA+kp+1],&Al[m*SA+kp+1]);
        }
        {
            int n = tid>>1, qq = tid&1;
            const uint4* sh = (const uint4*)(Wh + (size_t)n*hw + (k0>>1)) + qq*2;
            const uint4* sl = (const uint4*)(Wl + (size_t)n*hw + (k0>>1)) + qq*2;
            uint4 h0=sh[0], h1=sh[1], l0=sl[0], l1=sl[1];
            uint32_t* dh = &Bh[n*SA + qq*8];
            uint32_t* dl = &Bl[n*SA + qq*8];
            dh[0]=h0.x; dh[1]=h0.y; dh[2]=h0.z; dh[3]=h0.w;
            dh[4]=h1.x; dh[5]=h1.y; dh[6]=h1.z; dh[7]=h1.w;
            dl[0]=l0.x; dl[1]=l0.y; dl[2]=l0.z; dl[3]=l0.w;
            dl[4]=l1.x; dl[5]=l1.y; dl[6]=l1.z; dl[7]=l1.w;
        }
        __syncthreads();
        #pragma unroll
        for (int ks=0; ks<2; ks++){
            uint32_t ah[2][4], al[2][4];
            #pragma unroll
            for (int mt=0; mt<2; mt++){
                int r0 = (warp_m*32+mt*16+g)*SA + ks*8 + tig;
                int r1 = r0 + 8*SA;
                ah[mt][0]=Ah[r0]; ah[mt][1]=Ah[r1]; ah[mt][2]=Ah[r0+4]; ah[mt][3]=Ah[r1+4];
                al[mt][0]=Al[r0]; al[mt][1]=Al[r1]; al[mt][2]=Al[r0+4]; al[mt][3]=Al[r1+4];
            }
            #pragma unroll
            for (int nt=0; nt<8; nt++){
                int nb = (warp_n*64+nt*8+g)*SA + ks*8 + tig;
                uint32_t bh0=Bh[nb], bh1=Bh[nb+4], bl0=Bl[nb], bl1=Bl[nb+4];
                #pragma unroll
                for (int mt=0; mt<2; mt++){
                    MMA_BF16(acc[mt][nt], ah[mt], bh0, bh1);
                    MMA_BF16(acc[mt][nt], ah[mt], bl0, bl1);
                    MMA_BF16(acc[mt][nt], al[mt], bh0, bh1);
                }
            }
        }
        __syncthreads();
    }
    #pragma unroll
    for (int mt=0; mt<2; mt++){
        int rm0 = m0 + warp_m*32 + mt*16 + g;
        int rm1 = rm0 + 8;
        #pragma unroll
        for (int nt=0; nt<8; nt++){
            int col = warp_n*64 + nt*8 + 2*tig;
            float bb0 = __ldg(Bias+col), bb1 = __ldg(Bias+col+1);
            float o0=acc[mt][nt][0]+bb0, o1=acc[mt][nt][1]+bb1;
            float o2=acc[mt][nt][2]+bb0, o3=acc[mt][nt][3]+bb1;
            if (relu){ o0=fmaxf(o0,0.f); o1=fmaxf(o1,0.f); o2=fmaxf(o2,0.f); o3=fmaxf(o3,0.f); }
            if (rm0 < M) *(float2*)(Y + (size_t)rm0*128 + col) = make_float2(o0,o1);
            if (rm1 < M) *(float2*)(Y + (size_t)rm1*128 + col) = make_float2(o2,o3);
        }
    }
}

__global__ void __launch_bounds__(256,2)
k_gemm_bf16_n64(const float* __restrict__ X1, const float* __restrict__ X2, float scale2,
                int K1, int K2,
                const uint32_t* __restrict__ Wh, const uint32_t* __restrict__ Wl,
                const float* __restrict__ Bias,
                float* __restrict__ Y, int M, int Kp, int relu)
{
    __shared__ uint32_t Ah[128*SA], Al[128*SA], Bh[64*SA], Bl[64*SA];
    int tid = threadIdx.x, lane = tid&31, wid = tid>>5;
    int g = lane>>2, tig = lane&3;
    int m0 = blockIdx.x*128;
    int hw = Kp>>1;

    float acc[8][4];
    #pragma unroll
    for (int b=0;b<8;b++)
        #pragma unroll
        for (int cc=0;cc<4;cc++) acc[b][cc]=0.f;

    int m = tid>>1, q = tid&1, gm = m0+m;
    for (int k0=0; k0<Kp; k0+=32){
        #pragma unroll
        for (int h=0; h<4; h++){
            int c = k0 + (q*4+h)*4;
            float4 v = {0.f,0.f,0.f,0.f};
            if (gm < M){
                if (c < K1) v = *(const float4*)(X1 + (size_t)gm*K1 + c);
                else if (c < K1+K2){
                    v = *(const float4*)(X2 + (size_t)gm*K2 + (c-K1));
                    v.x*=scale2; v.y*=scale2; v.z*=scale2; v.w*=scale2;
                }
            }
            int kp = (q*4+h)*2;
            pack2(v.x,v.y,&Ah[m*SA+kp],  &Al[m*SA+kp]);
            pack2(v.z,v.w,&Ah[m*SA+kp+1],&Al[m*SA+kp+1]);
        }
        {
            int n = tid>>2, qq = tid&3;
            const uint4* sh = (const uint4*)(Wh + (size_t)n*hw + (k0>>1)) + qq;
            const uint4* sl = (const uint4*)(Wl + (size_t)n*hw + (k0>>1)) + qq;
            uint4 h0=sh[0], l0=sl[0];
            uint32_t* dh = &Bh[n*SA + qq*4];
            uint32_t* dl = &Bl[n*SA + qq*4];
            dh[0]=h0.x; dh[1]=h0.y; dh[2]=h0.z; dh[3]=h0.w;
            dl[0]=l0.x; dl[1]=l0.y; dl[2]=l0.z; dl[3]=l0.w;
        }
        __syncthreads();
        #pragma unroll
        for (int ks=0; ks<2; ks++){
            uint32_t ah[4], al[4];
            {
                int r0 = (wid*16+g)*SA + ks*8 + tig;
                int r1 = r0 + 8*SA;
                ah[0]=Ah[r0]; ah[1]=Ah[r1]; ah[2]=Ah[r0+4]; ah[3]=Ah[r1+4];
                al[0]=Al[r0]; al[1]=Al[r1]; al[2]=Al[r0+4]; al[3]=Al[r1+4];
            }
            #pragma unroll
            for (int nt=0; nt<8; nt++){
                int nb = (nt*8+g)*SA + ks*8 + tig;
                uint32_t bh0=Bh[nb], bh1=Bh[nb+4], bl0=Bl[nb], bl1=Bl[nb+4];
                MMA_BF16(acc[nt], ah, bh0, bh1);
                MMA_BF16(acc[nt], ah, bl0, bl1);
                MMA_BF16(acc[nt], al, bh0, bh1);
            }
        }
        __syncthreads();
    }
    int rm0 = m0 + wid*16 + g;
    int rm1 = rm0 + 8;
    #pragma unroll
    for (int nt=0; nt<8; nt++){
        int col = nt*8 + 2*tig;
        float bb0 = __ldg(Bias+col), bb1 = __ldg(Bias+col+1);
        float o0=acc[nt][0]+bb0, o1=acc[nt][1]+bb1;
        float o2=acc[nt][2]+bb0, o3=acc[nt][3]+bb1;
        if (relu){ o0=fmaxf(o0,0.f); o1=fmaxf(o1,0.f); o2=fmaxf(o2,0.f); o3=fmaxf(o3,0.f); }
        if (rm0 < M) *(float2*)(Y + (size_t)rm0*64 + col) = make_float2(o0,o1);
        if (rm1 < M) *(float2*)(Y + (size_t)rm1*64 + col) = make_float2(o2,o3);
    }
}

// fused: pn_apply(variables) -> o-MLP layer1 (relu) -> logits dot -> logits/last_logits
// proper k0 in {0,32} loop covering full K=64.
__global__ void __launch_bounds__(256,2)
k_fused_o(const int* __restrict__ vgid,
          const uint32_t* __restrict__ Wh, const uint32_t* __restrict__ Wl,
          const float* __restrict__ Bias,
          const float* __restrict__ ow2, const float* __restrict__ ob2)
{
    __shared__ uint32_t Ah[128*SA], Al[128*SA], Bh[64*SA], Bl[64*SA];
    int tid = threadIdx.x, lane = tid&31, wid = tid>>5;
    int g = lane>>2, tig = lane&3;
    int m0 = blockIdx.x*128;
    if (blockIdx.x==0 && tid==0) d_allsat = 1;
    int done = d_done;

    float acc[8][4];
    #pragma unroll
    for (int b=0;b<8;b++)
        #pragma unroll
        for (int cc=0;cc<4;cc++) acc[b][cc]=0.f;

    int m = tid>>1, q = tid&1, gm = m0+m;
    float rs = 0.f; const float* mrow = nullptr;
    if (gm < NV){
        int gg = vgid[gm];
        rs = rsqrtf(d_varred[gg]+1e-6f)*0.25f;
        mrow = &d_mean[gg*64];
    }

    for (int k0=0; k0<64; k0+=32){
        // stage A with fused pair_norm apply (each column transformed exactly once)
        #pragma unroll
        for (int h=0; h<4; h++){
            int c = k0 + (q*4+h)*4;
            float4 v = {0.f,0.f,0.f,0.f};
            if (gm < NV){
                float4 vv = *(const float4*)(d_variables + (size_t)gm*64 + c);
                if (done) v = vv;
                else {
                    float4 u = *(const float4*)(d_uout + (size_t)gm*64 + c);
                    v.x = (u.x - mrow[c  ])*rs + 0.1f*vv.x;
                    v.y = (u.y - mrow[c+1])*rs + 0.1f*vv.y;
                    v.z = (u.z - mrow[c+2])*rs + 0.1f*vv.z;
                    v.w = (u.w - mrow[c+3])*rs + 0.1f*vv.w;
                    *(float4*)(d_variables + (size_t)gm*64 + c) = v;
                }
            }
            int kp = (q*4+h)*2;
            pack2(v.x,v.y,&Ah[m*SA+kp],  &Al[m*SA+kp]);
            pack2(v.z,v.w,&Ah[m*SA+kp+1],&Al[m*SA+kp+1]);
        }
        // stage B (K tile of 32 -> 16 words per n row)
        {
            int n = tid>>2, qq = tid&3;
            const uint4* sh = (const uint4*)(Wh + (size_t)n*32 + (k0>>1)) + qq;
            const uint4* sl = (const uint4*)(Wl + (size_t)n*32 + (k0>>1)) + qq;
            uint4 h0=sh[0], l0=sl[0];
            uint32_t* dh = &Bh[n*SA + qq*4];
            uint32_t* dl = &Bl[n*SA + qq*4];
            dh[0]=h0.x; dh[1]=h0.y; dh[2]=h0.z; dh[3]=h0.w;
            dl[0]=l0.x; dl[1]=l0.y; dl[2]=l0.z; dl[3]=l0.w;
        }
        __syncthreads();
        #pragma unroll
        for (int ks=0; ks<2; ks++){
            uint32_t ah[4], al[4];
            {
                int r0 = (wid*16+g)*SA + ks*8 + tig;
                int r1 = r0 + 8*SA;
                ah[0]=Ah[r0]; ah[1]=Ah[r1]; ah[2]=Ah[r0+4]; ah[3]=Ah[r1+4];
                al[0]=Al[r0]; al[1]=Al[r1]; al[2]=Al[r0+4]; al[3]=Al[r1+4];
            }
            #pragma unroll
            for (int nt=0; nt<8; nt++){
                int nb = (nt*8+g)*SA + ks*8 + tig;
                uint32_t bh0=Bh[nb], bh1=Bh[nb+4], bl0=Bl[nb], bl1=Bl[nb+4];
                MMA_BF16(acc[nt], ah, bh0, bh1);
                MMA_BF16(acc[nt], ah, bl0, bl1);
                MMA_BF16(acc[nt], al, bh0, bh1);
            }
        }
        __syncthreads();
    }
    // epilogue: relu + dot with ow2, quad reduce, write logits
    float p0=0.f, p1=0.f;
    #pragma unroll
    for (int nt=0; nt<8; nt++){
        int col = nt*8 + 2*tig;
        float bb0 = __ldg(Bias+col), bb1 = __ldg(Bias+col+1);
        float w0 = __ldg(ow2+col),  w1 = __ldg(ow2+col+1);
        float o0=fmaxf(acc[nt][0]+bb0,0.f), o1=fmaxf(acc[nt][1]+bb1,0.f);
        float o2=fmaxf(acc[nt][2]+bb0,0.f), o3=fmaxf(acc[nt][3]+bb1,0.f);
        p0 += o0*w0 + o1*w1;
        p1 += o2*w0 + o3*w1;
    }
    p0 += __shfl_xor_sync(0xffffffffu, p0, 1);
    p0 += __shfl_xor_sync(0xffffffffu, p0, 2);
    p1 += __shfl_xor_sync(0xffffffffu, p1, 1);
    p1 += __shfl_xor_sync(0xffffffffu, p1, 2);
    if (tig==0){
        float ob = __ldg(ob2);
        int rm0 = m0 + wid*16 + g, rm1 = rm0 + 8;
        if (rm0 < NV){
            float lg = p0 + ob;
            d_logits[rm0] = lg;
            if (!done) d_last_logits[rm0] = lg;
        }
        if (rm1 < NV){
            float lg = p1 + ob;
            d_logits[rm1] = lg;
            if (!done) d_last_logits[rm1] = lg;
        }
    }
}

// ---------------- per-round kernels ----------------
__global__ void k_clause_cval(const int* __restrict__ elit, const float* __restrict__ wsig){
    int gw = (blockIdx.x*blockDim.x + threadIdx.x)>>5;
    int lane = threadIdx.x & 31;
    if (gw >= NC) return;
    int c = gw;
    float w = wsig[c];
    float2 acc = {0.f,0.f};
    #pragma unroll
    for (int j=0;j<3;j++){
        int l = elit[3*c+j];
        int v = (l<NV)? l : l-NV;
        float sgn = (l<NV)? 1.f : -1.f;
        float2 qv = *(const float2*)(d_query + (size_t)v*64 + lane*2);
        acc.x += sp_f(sgn*qv.x);
        acc.y += sp_f(sgn*qv.y);
    }
    float2 cl = { expf(-w*acc.x), expf(-w*acc.y) };
    *(float2*)(d_closs + (size_t)c*64 + lane*2) = cl;
}

__global__ void k_var_grad(const float* __restrict__ wsig){
    int gw = (blockIdx.x*blockDim.x + threadIdx.x)>>5;
    int lane = threadIdx.x & 31;
    if (gw >= NV) return;
    int v = gw;
    float2 ap={0.f,0.f}, an={0.f,0.f};
    int s0=d_csroff[v], e0=d_csroff[v+1];
    for (int i=s0;i<e0;i++){
        int c = d_csrclause[i];
        float w=wsig[c];
        float2 cl=*(const float2*)(d_closs+(size_t)c*64+lane*2);
        ap.x += w*cl.x; ap.y += w*cl.y;
    }
    int s1=d_csroff[NV+v], e1=d_csroff[NV+v+1];
    for (int i=s1;i<e1;i++){
        int c = d_csrclause[i];
        float w=wsig[c];
        float2 cl=*(const float2*)(d_closs+(size_t)c*64+lane*2);
        an.x += w*cl.x; an.y += w*cl.y;
    }
    float2 qv = *(const float2*)(d_query + (size_t)v*64 + lane*2);
    float vd = d_vdw[v];
    float2 gg;
    gg.x = (-ap.x*sigm(qv.x) + an.x*sigm(-qv.x)) * vd;
    gg.y = (-ap.y*sigm(qv.y) + an.y*sigm(-qv.y)) * vd;
    *(float2*)(d_unit + (size_t)v*256 + lane*2) = gg;
    float2 vv = *(const float2*)(d_variables + (size_t)v*64 + lane*2);
    *(float2*)(d_unit + (size_t)v*256 + 64 + lane*2) = vv;
}

__global__ void k_pn_stats(int mode){
    const float* x; const float* w; const int* st; int stride;
    if (mode==0){ x=d_cdata+64; w=d_cg_norm; st=d_cstart; stride=128; }
    else        { x=d_uout;    w=d_vg_norm; st=d_vstart; stride=64;  }
    int g=blockIdx.x;
    int s=st[g], e=st[g+1];
    int f=threadIdx.x&63, grp=threadIdx.x>>6;
    float s1=0.f, s2=0.f;
    for (int r=s+grp; r<e; r+=4){
        float wr = w[r];
        float xv = x[(size_t)r*stride+f];
        float wx = wr*xv;
        s1 += wx; s2 += wx*xv;
    }
    __shared__ float r1[256], r2[256];
    r1[threadIdx.x]=s1; r2[threadIdx.x]=s2; __syncthreads();
    if (threadIdx.x<64){
        float S1 = r1[f]+r1[64+f]+r1[128+f]+r1[192+f];
        float S2 = r2[f]+r2[64+f]+r2[128+f]+r2[192+f];
        d_mean[g*64+f]=S1;
        r1[f] = S2 - S1*S1;
    }
    __syncthreads();
    if (threadIdx.x<32){
        float v = r1[threadIdx.x]+r1[threadIdx.x+32];
        for (int o=16;o;o>>=1) v += __shfl_down_sync(0xffffffffu, v, o);
        if (threadIdx.x==0) d_varred[g]=v*(1.f/64.f);
    }
}

__global__ void k_pn_apply_c(const int* __restrict__ gid){
    if (d_done) return;
    int i = blockIdx.x*blockDim.x + threadIdx.x;
    if (i >= NC*64) return;
    int r = i>>6, f = i&63;
    int g = gid[r];
    float xc = d_cdata[(size_t)r*128 + 64 + f] - d_mean[g*64+f];
    float nrm = xc * rsqrtf(d_varred[g]+1e-6f) * 0.25f;
    d_clause_state[i] = nrm + 0.1f*d_clause_state[i];
}

__global__ void k_var_loss(const float* __restrict__ wsig){
    int gw = (blockIdx.x*blockDim.x + threadIdx.x)>>5;
    int lane = threadIdx.x & 31;
    if (gw >= NV) return;
    int v = gw;
    float2 ap={0.f,0.f}, an={0.f,0.f};
    int s0=d_csroff[v], e0=d_csroff[v+1];
    for (int i=s0;i<e0;i++){
        int c = d_csrclause[i];
        float w=wsig[c];
        float2 cl=*(const float2*)(d_cdata+(size_t)c*128+lane*2);
        ap.x += w*cl.x; ap.y += w*cl.y;
    }
    int s1=d_csroff[NV+v], e1=d_csroff[NV+v+1];
    for (int i=s1;i<e1;i++){
        int c = d_csrclause[i];
        float w=wsig[c];
        float2 cl=*(const float2*)(d_cdata+(size_t)c*128+lane*2);
        an.x += w*cl.x; an.y += w*cl.y;
    }
    float dp = d_degw[v], dn = d_degw[NV+v];
    *(float2*)(d_unit + (size_t)v*256 + 128 + lane*2) = make_float2(ap.x*dp, ap.y*dp);
    *(float2*)(d_unit + (size_t)v*256 + 192 + lane*2) = make_float2(an.x*dn, an.y*dn);
}

__global__ void k_final_clause(const int* __restrict__ elit, const float* __restrict__ wsig){
    int g = blockIdx.x;
    int s = d_cstart[g], e = d_cstart[g+1];
    float lsum=0.f; int sat=1;
    for (int c=s+threadIdx.x; c<e; c+=blockDim.x){
        float w = wsig[c];
        float cvs=0.f, csat=0.f;
        #pragma unroll
        for (int j=0;j<3;j++){
            int l = elit[3*c+j];
            int v = (l<NV)? l : l-NV;
            float sgn = (l<NV)? 1.f : -1.f;
            float lg = d_logits[v];
            cvs += sp_f(sgn*lg);
            float a = (lg>0.f)? 1.f : 0.f;
            float lit01 = (l<NV)? a : 1.f-a;
            csat += w*lit01;
        }
        float cv = expf(-w*cvs);
        float pc = cv * (-logf(1.f - cv + 1e-10f));
        lsum += pc*w;
        if (csat < 1.f) sat = 0;
    }
    __shared__ float sred[256];
    __shared__ int ssat[256];
    sred[threadIdx.x]=lsum; ssat[threadIdx.x]=sat; __syncthreads();
    for (int o=128;o;o>>=1){
        if (threadIdx.x<o){ sred[threadIdx.x]+=sred[threadIdx.x+o]; ssat[threadIdx.x]&=ssat[threadIdx.x+o]; }
        __syncthreads();
    }
    if (threadIdx.x==0){
        d_pg[g]=sred[0];
        if (!ssat[0]) d_allsat = 0;
    }
}

__global__ void k_finish(){
    int done0 = d_done;
    if (!done0){
        for (int g=threadIdx.x; g<NG; g+=blockDim.x)
            d_loss_sum[g] += sqrtf(d_pg[g]+1e-6f) - 0.001f;
    }
    __syncthreads();
    if (threadIdx.x==0 && !done0){
        d_step++;
        if (d_allsat) d_done = 1;
    }
}

__global__ void k_output(float* __restrict__ out, int n){
    int i = blockIdx.x*blockDim.x + threadIdx.x;
    if (i >= n) return;
    float v;
    if (i < NV)            v = d_last_logits[i];
    else if (i < NV+NG)    v = d_loss_sum[i-NV]*(1.f/(float)RNDS);
    else if (i == NV+NG)   v = (float)d_step;
    else                   v = 0.f;
    out[i] = v;
}

// ---------------- host ----------------
extern "C" void kernel_launch(void* const* d_in, const int* in_sizes, int n_in,
                              void* d_out, int out_size){
    const float* wsig   = (const float*)d_in[0];
    const float* wsp    = (const float*)d_in[1];
    const float* noise  = (const float*)d_in[2];
    const int*   elit   = (const int*)d_in[3];
    const int*   eclause= (const int*)d_in[4];
    const int*   cgid   = (const int*)d_in[5];
    const int*   vgid   = (const int*)d_in[6];
    const float* P[18];
    for (int i=0;i<18;i++) P[i]=(const float*)d_in[7+i];
    const float *qw1=P[0],*qb1=P[1],*qw2=P[2],*qb2=P[3];
    const float *cw1=P[4],*cb1=P[5],*cw2=P[6],*cb2=P[7];
    const float *uw1=P[8],*ub1=P[9],*uw2=P[10],*ub2=P[11],*uw3=P[12],*ub3=P[13];
    const float *ow1=P[14],*ob1=P[15],*ow2=P[16],*ob2=P[17];

    float *p_hq,*p_query,*p_hc,*p_cdata,*p_unit,*p_hu1,*p_hu2,*p_uout,*p_vars,*p_cs,*p_closs;
    uint32_t *p_wh, *p_wl;
    cudaGetSymbolAddress((void**)&p_hq,    d_hq);
    cudaGetSymbolAddress((void**)&p_query, d_query);
    cudaGetSymbolAddress((void**)&p_hc,    d_hc);
    cudaGetSymbolAddress((void**)&p_cdata, d_cdata);
    cudaGetSymbolAddress((void**)&p_unit,  d_unit);
    cudaGetSymbolAddress((void**)&p_hu1,   d_hu1);
    cudaGetSymbolAddress((void**)&p_hu2,   d_hu2);
    cudaGetSymbolAddress((void**)&p_uout,  d_uout);
    cudaGetSymbolAddress((void**)&p_vars,  d_variables);
    cudaGetSymbolAddress((void**)&p_cs,    d_clause_state);
    cudaGetSymbolAddress((void**)&p_closs, d_closs);
    cudaGetSymbolAddress((void**)&p_wh,    d_wh);
    cudaGetSymbolAddress((void**)&p_wl,    d_wl);

    const int GV = CEILDIV(NV,128);   // 157
    const int GC = CEILDIV(NC,128);   // 657

    // packed-weight offsets (words)
    const int OQ1=0, OQ2=3072, OC1=5120, OC2=13312, OU1=21504, OU2=37888, OU3=46080, OO1=50176;

    // ---- init / precompute ----
    k_init<<<CEILDIV(2*NV,256),256>>>();
    k_init_state<<<CEILDIV(NC*64,256),256>>>();
    k_edge_scatter<<<CEILDIV(NE,256),256>>>(elit, eclause, wsig, wsp);
    k_scan<<<1,1024>>>();
    k_fill<<<CEILDIV(NE,256),256>>>(elit);
    k_segmin<<<CEILDIV(NC,256),256>>>(cgid, vgid);
    k_segfix<<<1,32>>>();
    k_var_pre<<<CEILDIV(NV,256),256>>>(vgid);
    k_clause_pre<<<CEILDIV(NC,256),256>>>(cgid, wsig);
    k_norms<<<CEILDIV(NC,256),256>>>(cgid, vgid, wsig);

    // ---- pack weights (hi/lo bf16, [N][Kp/2]) ----
    k_pack_w<<<CEILDIV(64*48,256),256>>>(qw1,  68, 64, 96, p_wh+OQ1, p_wl+OQ1);
    k_pack_w<<<CEILDIV(64*32,256),256>>>(qw2,  64, 64, 64, p_wh+OQ2, p_wl+OQ2);
    k_pack_w<<<CEILDIV(128*64,256),256>>>(cw1, 128,128,128, p_wh+OC1, p_wl+OC1);
    k_pack_w<<<CEILDIV(128*64,256),256>>>(cw2, 128,128,128, p_wh+OC2, p_wl+OC2);
    k_pack_w<<<CEILDIV(128*128,256),256>>>(uw1,256,128,256, p_wh+OU1, p_wl+OU1);
    k_pack_w<<<CEILDIV(128*64,256),256>>>(uw2, 128,128,128, p_wh+OU2, p_wl+OU2);
    k_pack_w<<<CEILDIV(64*64,256),256>>>(uw3, 128, 64,128, p_wh+OU3, p_wl+OU3);
    k_pack_w<<<CEILDIV(64*32,256),256>>>(ow1,  64, 64, 64, p_wh+OO1, p_wl+OO1);

    // ---- rounds ----
    for (int t=0; t<RNDS; t++){
        const float* nt = noise + (size_t)t*NV*4;
        k_gemm_bf16_n64<<<GV,256>>>(p_vars, nt, 1.f, 64, 4, p_wh+OQ1, p_wl+OQ1, qb1, p_hq, NV, 96, 1);
        k_gemm_bf16_n64<<<GV,256>>>(p_hq, nullptr, 0.f, 64, 0, p_wh+OQ2, p_wl+OQ2, qb2, p_query, NV, 64, 0);
        k_clause_cval<<<CEILDIV(NC*32,256),256>>>(elit, wsig);
        k_var_grad<<<CEILDIV(NV*32,256),256>>>(wsig);
        k_gemm_bf16_n128<<<GC,256>>>(p_cs, p_closs, 4.f, 64, 64, p_wh+OC1, p_wl+OC1, cb1, p_hc, NC, 128, 1);
        k_gemm_bf16_n128<<<GC,256>>>(p_hc, nullptr, 0.f, 128, 0, p_wh+OC2, p_wl+OC2, cb2, p_cdata, NC, 128, 0);
        k_pn_stats<<<NG,256>>>(0);
        k_pn_apply_c<<<CEILDIV(NC*64,256),256>>>(cgid);
        k_var_loss<<<CEILDIV(NV*32,256),256>>>(wsig);
        k_gemm_bf16_n128<<<GV,256>>>(p_unit, nullptr, 0.f, 256, 0, p_wh+OU1, p_wl+OU1, ub1, p_hu1, NV, 256, 1);
        k_gemm_bf16_n128<<<GV,256>>>(p_hu1, nullptr, 0.f, 128, 0, p_wh+OU2, p_wl+OU2, ub2, p_hu2, NV, 128, 1);
        k_gemm_bf16_n64 <<<GV,256>>>(p_hu2, nullptr, 0.f, 128, 0, p_wh+OU3, p_wl+OU3, ub3, p_uout, NV, 128, 0);
        k_pn_stats<<<NG,256>>>(1);
        k_fused_o<<<GV,256>>>(vgid, p_wh+OO1, p_wl+OO1, ob1, ow2, ob2);
        k_final_clause<<<NG,256>>>(elit, wsig);
        k_finish<<<1,256>>>();
    }

    k_output<<<CEILDIV(out_size>0?out_size:1,256),256>>>((float*)d_out, out_size);
}